// round 1
// baseline (speedup 1.0000x reference)
#include <cuda_runtime.h>
#include <math.h>

// Problem constants
#define EDIM 1024
#define HN   16
#define DHD  64
#define DFFD 4096
#define NLE  4
#define NLD  4
#define NB   4
#define SEQ  512
#define NROWS (NB*SEQ)     // 2048
#define NBH   (NB*HN)      // 64

// ---------------- scratch (static device globals; no allocations) ----------
__device__ float g_x [NB*SEQ*EDIM];     // encoder state (B,S,E)
__device__ float g_y [NB*SEQ*EDIM];     // decoder state (B,S,E)
__device__ float g_q [NBH*SEQ*DHD];     // (B,H,S,DH)
__device__ float g_k [NBH*SEQ*DHD];
__device__ float g_v [NBH*SEQ*DHD];
__device__ float g_p [(long long)NBH*SEQ*SEQ]; // attention scores (B,H,S,T)
__device__ float g_t1[NB*SEQ*EDIM];     // head-concat attention output
__device__ float g_t2[NB*SEQ*EDIM];     // projection / ffn delta
__device__ float g_ff[NB*SEQ*DFFD];     // ffn hidden

// ---------------- block reductions -----------------------------------------
__device__ __forceinline__ float blockReduceSum(float v) {
    __shared__ float sh[32];
    int lane = threadIdx.x & 31, w = threadIdx.x >> 5, nw = blockDim.x >> 5;
    #pragma unroll
    for (int o = 16; o; o >>= 1) v += __shfl_xor_sync(0xffffffffu, v, o);
    if (lane == 0) sh[w] = v;
    __syncthreads();
    if (w == 0) {
        float t = (lane < nw) ? sh[lane] : 0.f;
        #pragma unroll
        for (int o = 16; o; o >>= 1) t += __shfl_xor_sync(0xffffffffu, t, o);
        if (lane == 0) sh[0] = t;
    }
    __syncthreads();
    float r = sh[0];
    __syncthreads();
    return r;
}

__device__ __forceinline__ float blockReduceMax(float v) {
    __shared__ float sh[32];
    int lane = threadIdx.x & 31, w = threadIdx.x >> 5, nw = blockDim.x >> 5;
    #pragma unroll
    for (int o = 16; o; o >>= 1) v = fmaxf(v, __shfl_xor_sync(0xffffffffu, v, o));
    if (lane == 0) sh[w] = v;
    __syncthreads();
    if (w == 0) {
        float t = (lane < nw) ? sh[lane] : -INFINITY;
        #pragma unroll
        for (int o = 16; o; o >>= 1) t = fmaxf(t, __shfl_xor_sync(0xffffffffu, t, o));
        if (lane == 0) sh[0] = t;
    }
    __syncthreads();
    float r = sh[0];
    __syncthreads();
    return r;
}

// ---------------- layout swap (S,B,E) <-> (B,S,E) ---------------------------
__global__ void reorder_k(const float* __restrict__ in, float* __restrict__ out, int toBS) {
    int s = blockIdx.x, b = blockIdx.y;
    long long r_sb = ((long long)s * NB + b) * EDIM;
    long long r_bs = ((long long)b * SEQ + s) * EDIM;
    const float4* src = (const float4*)(in  + (toBS ? r_sb : r_bs));
    float4*       dst = (float4*)      (out + (toBS ? r_bs : r_sb));
    for (int i = threadIdx.x; i < EDIM / 4; i += blockDim.x) dst[i] = src[i];
}

// ---------------- generic SGEMM ---------------------------------------------
// bMode: 0 = B row-major [k*ldb + n]
//        1 = head-sliced weight (H,E,DH): addr = (n>>6)*K*64 + k*64 + (n&63)
//        2 = B transposed [n*ldb + k]  (for Q*K^T)
// cMode: 0 = C[z*sCz + m*ldc + n]
//        1 = qkv scatter: m=(b,s) n=(h,d) -> ((b*HN+h)*SEQ+s)*DHD + d
//        2 = head concat: z=(b,h)        -> ((b*SEQ+m))*EDIM + h*DHD + n
// epilogue: *scale, +bias, -inf mask (mA[m*N+n] + mP[b*N+n] is -inf), relu
template<int BM, int BN, int BK, int TM, int TN>
__global__ void gemm_k(const float* __restrict__ A, const float* __restrict__ Bm,
                       const float* __restrict__ bias, float* __restrict__ C,
                       int M, int N, int K, int lda, int ldb, int ldc,
                       long long sAz, long long sBz, long long sCz,
                       int bMode, int cMode, int relu, float scale,
                       const float* __restrict__ mA, const float* __restrict__ mP)
{
    constexpr int TX = BN / TN, TY = BM / TM, THREADS = TX * TY;
    __shared__ float sA[BK][BM];
    __shared__ float sB[BK][BN];
    const int z = blockIdx.z;
    const float* Ab = A + (long long)z * sAz;
    const float* Bb = Bm + (long long)z * sBz;
    const int tid = threadIdx.x;
    const int tcx = tid % TX, tcy = tid / TX;
    const int row0 = blockIdx.y * BM, col0 = blockIdx.x * BN;

    float acc[TM][TN];
    #pragma unroll
    for (int i = 0; i < TM; i++)
        #pragma unroll
        for (int j = 0; j < TN; j++) acc[i][j] = 0.f;

    for (int k0 = 0; k0 < K; k0 += BK) {
        #pragma unroll
        for (int l = 0; l < (BM * BK) / (THREADS * 4); l++) {
            int idx = (l * THREADS + tid) * 4;
            int ar = idx / BK, ac = idx % BK;
            float4 va = *(const float4*)(Ab + (long long)(row0 + ar) * lda + k0 + ac);
            sA[ac + 0][ar] = va.x; sA[ac + 1][ar] = va.y;
            sA[ac + 2][ar] = va.z; sA[ac + 3][ar] = va.w;
        }
        if (bMode == 0) {
            #pragma unroll
            for (int l = 0; l < (BK * BN) / (THREADS * 4); l++) {
                int idx = (l * THREADS + tid) * 4;
                int br = idx / BN, bc = idx % BN;
                *(float4*)&sB[br][bc] =
                    *(const float4*)(Bb + (long long)(k0 + br) * ldb + col0 + bc);
            }
        } else if (bMode == 1) {
            #pragma unroll
            for (int l = 0; l < (BK * BN) / (THREADS * 4); l++) {
                int idx = (l * THREADS + tid) * 4;
                int br = idx / BN, bc = idx % BN;
                int n = col0 + bc; int h = n >> 6, dl = n & 63;
                *(float4*)&sB[br][bc] =
                    *(const float4*)(Bb + (long long)h * K * 64 + (long long)(k0 + br) * 64 + dl);
            }
        } else {
            #pragma unroll
            for (int l = 0; l < (BK * BN) / (THREADS * 4); l++) {
                int idx = (l * THREADS + tid) * 4;
                int bc = idx / BK, bk = idx % BK;
                float4 vb = *(const float4*)(Bb + (long long)(col0 + bc) * ldb + k0 + bk);
                sB[bk + 0][bc] = vb.x; sB[bk + 1][bc] = vb.y;
                sB[bk + 2][bc] = vb.z; sB[bk + 3][bc] = vb.w;
            }
        }
        __syncthreads();
        #pragma unroll
        for (int kk = 0; kk < BK; kk++) {
            float ra[TM], rb[TN];
            #pragma unroll
            for (int i = 0; i < TM; i += 4)
                *(float4*)&ra[i] = *(const float4*)&sA[kk][tcy * TM + i];
            #pragma unroll
            for (int j = 0; j < TN; j += 4)
                *(float4*)&rb[j] = *(const float4*)&sB[kk][tcx * TN + j];
            #pragma unroll
            for (int i = 0; i < TM; i++)
                #pragma unroll
                for (int j = 0; j < TN; j++)
                    acc[i][j] = fmaf(ra[i], rb[j], acc[i][j]);
        }
        __syncthreads();
    }

    const int bz = z >> 4;  // batch index when z = b*HN + h
    #pragma unroll
    for (int i = 0; i < TM; i++) {
        int m = row0 + tcy * TM + i;
        #pragma unroll
        for (int j = 0; j < TN; j++) {
            int n = col0 + tcx * TN + j;
            float vv = acc[i][j] * scale;
            if (bias) vv += bias[n];
            if (mA || mP) {
                float mm = 0.f;
                if (mA) mm += mA[(long long)m * N + n];
                if (mP) mm += mP[bz * N + n];
                if (isinf(mm) && mm < 0.f) vv = -INFINITY;
            }
            if (relu) vv = fmaxf(vv, 0.f);
            if (cMode == 0) {
                C[(long long)z * sCz + (long long)m * ldc + n] = vv;
            } else if (cMode == 1) {
                int b = m >> 9, s = m & 511, h = n >> 6, d = n & 63;
                C[(((long long)(b * HN + h)) * SEQ + s) * DHD + d] = vv;
            } else {
                int h = z & 15;
                C[((long long)(bz * SEQ + m)) * EDIM + h * DHD + n] = vv;
            }
        }
    }
}

// ---------------- softmax over rows of length 512 ---------------------------
__global__ void softmax_k(float* __restrict__ p) {
    long long row = blockIdx.x;
    float* r = p + row * SEQ;
    int t = threadIdx.x;                  // 128 threads, 4 elems each
    float4 v = ((float4*)r)[t];
    float mx = fmaxf(fmaxf(v.x, v.y), fmaxf(v.z, v.w));
    mx = blockReduceMax(mx);
    float e0 = __expf(v.x - mx), e1 = __expf(v.y - mx);
    float e2 = __expf(v.z - mx), e3 = __expf(v.w - mx);
    float s = blockReduceSum(e0 + e1 + e2 + e3);
    float inv = 1.f / s;
    float4 o = make_float4(e0 * inv, e1 * inv, e2 * inv, e3 * inv);
    ((float4*)r)[t] = o;
}

// ---------------- fused residual + LayerNorm (in-place on x) ----------------
__global__ void ln_res_k(float* __restrict__ x, const float* __restrict__ d,
                         const float* __restrict__ g, const float* __restrict__ b)
{
    long long row = blockIdx.x;
    float* xr = x + row * EDIM;
    const float* dr = d + row * EDIM;
    int t = threadIdx.x;                  // 256 threads, 4 elems each
    float4 xv = ((float4*)xr)[t];
    float4 dv = ((const float4*)dr)[t];
    float v0 = xv.x + dv.x, v1 = xv.y + dv.y, v2 = xv.z + dv.z, v3 = xv.w + dv.w;
    float mean = blockReduceSum(v0 + v1 + v2 + v3) * (1.f / EDIM);
    float c0 = v0 - mean, c1 = v1 - mean, c2 = v2 - mean, c3 = v3 - mean;
    float var = blockReduceSum(c0 * c0 + c1 * c1 + c2 * c2 + c3 * c3) * (1.f / EDIM);
    float rstd = rsqrtf(var + 1e-5f);
    float4 gv = ((const float4*)g)[t];
    float4 bv = ((const float4*)b)[t];
    float4 o = make_float4(c0 * rstd * gv.x + bv.x, c1 * rstd * gv.y + bv.y,
                           c2 * rstd * gv.z + bv.z, c3 * rstd * gv.w + bv.w);
    ((float4*)xr)[t] = o;
}

// ---------------- host-side launch helpers ----------------------------------
static inline void g128(const float* A, const float* Bm, const float* bias, float* C,
                        int M, int N, int K, int lda, int ldb, int ldc,
                        long long sAz, long long sBz, long long sCz, int nz,
                        int bMode, int cMode, int relu, float scale,
                        const float* mA, const float* mP)
{
    dim3 grid(N / 128, M / 128, nz);
    gemm_k<128, 128, 8, 8, 8><<<grid, 256>>>(A, Bm, bias, C, M, N, K, lda, ldb, ldc,
                                             sAz, sBz, sCz, bMode, cMode, relu, scale, mA, mP);
}
static inline void g64(const float* A, const float* Bm, const float* bias, float* C,
                       int M, int N, int K, int lda, int ldb, int ldc,
                       long long sAz, long long sBz, long long sCz, int nz,
                       int bMode, int cMode, int relu, float scale,
                       const float* mA, const float* mP)
{
    dim3 grid(N / 64, M / 64, nz);
    gemm_k<64, 64, 16, 4, 4><<<grid, 256>>>(A, Bm, bias, C, M, N, K, lda, ldb, ldc,
                                            sAz, sBz, sCz, bMode, cMode, relu, scale, mA, mP);
}

static void attention(const float* qin, const float* kvin,
                      const float* wqkv, const float* wo, const float* bo,
                      const float* mA, const float* mP,
                      float* q, float* k, float* v, float* p, float* t1, float* t2)
{
    const long long WS = (long long)HN * EDIM * DHD;  // one of q/k/v weight slab
    // QKV projections (head-sliced weight layout, scatter to (B,H,S,DH))
    g128(qin,  wqkv,          nullptr, q, NROWS, EDIM, EDIM, EDIM, 0, 0, 0, 0, 0, 1,
         1, 1, 0, 1.f, nullptr, nullptr);
    g128(kvin, wqkv + WS,     nullptr, k, NROWS, EDIM, EDIM, EDIM, 0, 0, 0, 0, 0, 1,
         1, 1, 0, 1.f, nullptr, nullptr);
    g128(kvin, wqkv + 2 * WS, nullptr, v, NROWS, EDIM, EDIM, EDIM, 0, 0, 0, 0, 0, 1,
         1, 1, 0, 1.f, nullptr, nullptr);
    // scores = Q K^T / 8  (+ mask)
    g128(q, k, nullptr, p, SEQ, SEQ, DHD, DHD, DHD, SEQ,
         (long long)SEQ * DHD, (long long)SEQ * DHD, (long long)SEQ * SEQ, NBH,
         2, 0, 0, 0.125f, mA, mP);
    softmax_k<<<NBH * SEQ, 128>>>(p);
    // out = P V, scattered into head-concat layout (B,S,E)
    g64(p, v, nullptr, t1, SEQ, DHD, SEQ, SEQ, DHD, 0,
        (long long)SEQ * SEQ, (long long)SEQ * DHD, 0, NBH,
        0, 2, 0, 1.f, nullptr, nullptr);
    // output projection + bias -> t2 (delta for residual)
    g128(t1, wo, bo, t2, NROWS, EDIM, EDIM, EDIM, EDIM, EDIM, 0, 0, 0, 1,
         0, 0, 0, 1.f, nullptr, nullptr);
}

static void ffn_block(float* x, const float* w1, const float* b1,
                      const float* w2, const float* b2,
                      const float* lg, const float* lb, float* ff, float* t2)
{
    g128(x,  w1, b1, ff, NROWS, DFFD, EDIM, EDIM, DFFD, DFFD, 0, 0, 0, 1,
         0, 0, 1, 1.f, nullptr, nullptr);
    g128(ff, w2, b2, t2, NROWS, EDIM, DFFD, DFFD, EDIM, EDIM, 0, 0, 0, 1,
         0, 0, 0, 1.f, nullptr, nullptr);
    ln_res_k<<<NROWS, 256>>>(x, t2, lg, lb);
}

// ---------------- entry -----------------------------------------------------
extern "C" void kernel_launch(void* const* d_in, const int* in_sizes, int n_in,
                              void* d_out, int out_size)
{
    const float* src      = (const float*)d_in[0];
    const float* tgt      = (const float*)d_in[1];
    const float* src_mask = (const float*)d_in[2];
    const float* tgt_mask = (const float*)d_in[3];
    const float* src_pad  = (const float*)d_in[4];
    const float* tgt_pad  = (const float*)d_in[5];
    const float* enc_wqkv = (const float*)d_in[6];
    const float* enc_wo   = (const float*)d_in[7];
    const float* enc_bo   = (const float*)d_in[8];
    const float* enc_w1   = (const float*)d_in[9];
    const float* enc_b1   = (const float*)d_in[10];
    const float* enc_w2   = (const float*)d_in[11];
    const float* enc_b2   = (const float*)d_in[12];
    const float* enc_lg   = (const float*)d_in[13];
    const float* enc_lb   = (const float*)d_in[14];
    const float* dqkv_s   = (const float*)d_in[15];
    const float* dwo_s    = (const float*)d_in[16];
    const float* dbo_s    = (const float*)d_in[17];
    const float* dqkv_c   = (const float*)d_in[18];
    const float* dwo_c    = (const float*)d_in[19];
    const float* dbo_c    = (const float*)d_in[20];
    const float* dw1      = (const float*)d_in[21];
    const float* db1      = (const float*)d_in[22];
    const float* dw2      = (const float*)d_in[23];
    const float* db2      = (const float*)d_in[24];
    const float* dlg      = (const float*)d_in[25];
    const float* dlb      = (const float*)d_in[26];

    float *x, *y, *q, *k, *v, *p, *t1, *t2, *ff;
    cudaGetSymbolAddress((void**)&x,  g_x);
    cudaGetSymbolAddress((void**)&y,  g_y);
    cudaGetSymbolAddress((void**)&q,  g_q);
    cudaGetSymbolAddress((void**)&k,  g_k);
    cudaGetSymbolAddress((void**)&v,  g_v);
    cudaGetSymbolAddress((void**)&p,  g_p);
    cudaGetSymbolAddress((void**)&t1, g_t1);
    cudaGetSymbolAddress((void**)&t2, g_t2);
    cudaGetSymbolAddress((void**)&ff, g_ff);

    dim3 tg(SEQ, NB);
    reorder_k<<<tg, 256>>>(src, x, 1);
    reorder_k<<<tg, 256>>>(tgt, y, 1);

    const long long WL = (long long)3 * HN * EDIM * DHD;  // per-layer wqkv slab

    for (int l = 0; l < NLE; l++) {
        attention(x, x, enc_wqkv + l * WL,
                  enc_wo + (long long)l * EDIM * EDIM, enc_bo + l * EDIM,
                  src_mask, src_pad, q, k, v, p, t1, t2);
        ln_res_k<<<NROWS, 256>>>(x, t2, enc_lg + (l * 2 + 0) * EDIM, enc_lb + (l * 2 + 0) * EDIM);
        ffn_block(x, enc_w1 + (long long)l * EDIM * DFFD, enc_b1 + l * DFFD,
                  enc_w2 + (long long)l * DFFD * EDIM, enc_b2 + l * EDIM,
                  enc_lg + (l * 2 + 1) * EDIM, enc_lb + (l * 2 + 1) * EDIM, ff, t2);
    }

    for (int l = 0; l < NLD; l++) {
        // decoder self-attention (causal + pad mask)
        attention(y, y, dqkv_s + l * WL,
                  dwo_s + (long long)l * EDIM * EDIM, dbo_s + l * EDIM,
                  tgt_mask, tgt_pad, q, k, v, p, t1, t2);
        ln_res_k<<<NROWS, 256>>>(y, t2, dlg + (l * 3 + 0) * EDIM, dlb + (l * 3 + 0) * EDIM);
        // cross-attention (pad mask only); K/V from encoder output x
        attention(y, x, dqkv_c + l * WL,
                  dwo_c + (long long)l * EDIM * EDIM, dbo_c + l * EDIM,
                  nullptr, src_pad, q, k, v, p, t1, t2);
        ln_res_k<<<NROWS, 256>>>(y, t2, dlg + (l * 3 + 1) * EDIM, dlb + (l * 3 + 1) * EDIM);
        // FFN
        ffn_block(y, dw1 + (long long)l * EDIM * DFFD, db1 + l * DFFD,
                  dw2 + (long long)l * DFFD * EDIM, db2 + l * EDIM,
                  dlg + (l * 3 + 2) * EDIM, dlb + (l * 3 + 2) * EDIM, ff, t2);
    }

    reorder_k<<<tg, 256>>>(y, (float*)d_out, 0);
}

// round 3
// speedup vs baseline: 3.3062x; 3.3062x over previous
#include <cuda_runtime.h>
#include <math.h>
#include <stdint.h>

// Problem constants
#define EDIM 1024
#define HN   16
#define DHD  64
#define DFFD 4096
#define NLE  4
#define NLD  4
#define NB   4
#define SEQ  512
#define NROWS (NB*SEQ)     // 2048
#define NBH   (NB*HN)      // 64
#define QKVOFF (NBH*SEQ*DHD)   // one q/k/v slab: 64*512*64 = 2M floats

// ---------------- scratch (static device globals; no allocations) ----------
__device__ float g_x  [NB*SEQ*EDIM];
__device__ float g_y  [NB*SEQ*EDIM];
__device__ float g_qkv[3*QKVOFF];                 // q|k|v, each (B,H,S,DH)
__device__ float g_p  [(long long)NBH*SEQ*SEQ];   // scores (B,H,S,T)
__device__ float g_t1 [NB*SEQ*EDIM];
__device__ float g_t2 [NB*SEQ*EDIM];
__device__ float g_ff [NB*SEQ*DFFD];

// ---------------- small helpers ---------------------------------------------
__device__ __forceinline__ uint32_t f2tf(float x) {
    uint32_t r; asm("cvt.rna.tf32.f32 %0, %1;" : "=r"(r) : "f"(x)); return r;
}
__device__ __forceinline__ void mma_tf32(float* c, const uint32_t* a, const uint32_t* b) {
    asm volatile("mma.sync.aligned.m16n8k8.row.col.f32.tf32.tf32.f32 "
                 "{%0,%1,%2,%3},{%4,%5,%6,%7},{%8,%9},{%0,%1,%2,%3};"
                 : "+f"(c[0]), "+f"(c[1]), "+f"(c[2]), "+f"(c[3])
                 : "r"(a[0]), "r"(a[1]), "r"(a[2]), "r"(a[3]), "r"(b[0]), "r"(b[1]));
}

__device__ __forceinline__ float blockReduceSum(float v) {
    __shared__ float sh[32];
    int lane = threadIdx.x & 31, w = threadIdx.x >> 5, nw = blockDim.x >> 5;
    #pragma unroll
    for (int o = 16; o; o >>= 1) v += __shfl_xor_sync(0xffffffffu, v, o);
    if (lane == 0) sh[w] = v;
    __syncthreads();
    if (w == 0) {
        float t = (lane < nw) ? sh[lane] : 0.f;
        #pragma unroll
        for (int o = 16; o; o >>= 1) t += __shfl_xor_sync(0xffffffffu, t, o);
        if (lane == 0) sh[0] = t;
    }
    __syncthreads();
    float r = sh[0]; __syncthreads(); return r;
}
__device__ __forceinline__ float blockReduceMax(float v) {
    __shared__ float sh[32];
    int lane = threadIdx.x & 31, w = threadIdx.x >> 5, nw = blockDim.x >> 5;
    #pragma unroll
    for (int o = 16; o; o >>= 1) v = fmaxf(v, __shfl_xor_sync(0xffffffffu, v, o));
    if (lane == 0) sh[w] = v;
    __syncthreads();
    if (w == 0) {
        float t = (lane < nw) ? sh[lane] : -INFINITY;
        #pragma unroll
        for (int o = 16; o; o >>= 1) t = fmaxf(t, __shfl_xor_sync(0xffffffffu, t, o));
        if (lane == 0) sh[0] = t;
    }
    __syncthreads();
    float r = sh[0]; __syncthreads(); return r;
}

// ---------------- layout swap (S,B,E) <-> (B,S,E) ---------------------------
__global__ void reorder_k(const float* __restrict__ in, float* __restrict__ out, int toBS) {
    int s = blockIdx.x, b = blockIdx.y;
    long long r_sb = ((long long)s * NB + b) * EDIM;
    long long r_bs = ((long long)b * SEQ + s) * EDIM;
    const float4* src = (const float4*)(in  + (toBS ? r_sb : r_bs));
    float4*       dst = (float4*)      (out + (toBS ? r_bs : r_sb));
    for (int i = threadIdx.x; i < EDIM / 4; i += blockDim.x) dst[i] = src[i];
}

// ---------------- TF32 tensor-core GEMM --------------------------------------
// bMode (template): 0 = B row-major [k*ldb + n]
//                   1 = head-sliced weight: addr = (n>>6)*K*64 + k*64 + (n&63)
//                   2 = B transposed row-major [n*ldb + k]
// cMode (runtime):  0 = C[z*sCz + m*ldc + n]
//                   1 = qkv scatter with nOff into unified (3,B,H,S,DH) buffer
//                   2 = head concat: z=(b,h) -> ((b*SEQ+m))*EDIM + h*DHD + n
// epilogue: *scale, +bias[n], -inf mask (mA[m*N+n] + mP[bz*N+n] == -inf), relu
template<int BM, int BN, int BK, int WGM, int WGN, int MT, int NT, int bMode>
__global__ __launch_bounds__(256, 2)
void tmma_k(const float* __restrict__ A, const float* __restrict__ Bm,
            const float* __restrict__ bias, float* __restrict__ C,
            int M, int N, int K, int lda, int ldb, int ldc,
            long long sAz, long long sBz, long long sCz,
            int cMode, int relu, int nOff, float scale,
            const float* __restrict__ mA, const float* __restrict__ mP)
{
    constexpr int SAS  = BK + 4;   // sA stride (m-major rows)
    constexpr int SBS0 = BN + 8;   // sB stride for [k][n] layout
    constexpr int SBS2 = BK + 4;   // sB stride for [n][k] layout
    constexpr int SB_SZ = (BK * SBS0 > BN * SBS2) ? BK * SBS0 : BN * SBS2;
    constexpr int A_IT = (BM * BK) / 1024;
    constexpr int B_IT = (BK * BN) / 1024;

    __shared__ uint32_t sA[BM * SAS];
    __shared__ uint32_t sB[SB_SZ];

    const int z = blockIdx.z;
    const float* Ab = A  + (long long)z * sAz;
    const float* Bb = Bm + (long long)z * sBz;
    const int tid = threadIdx.x;
    const int row0 = blockIdx.y * BM, col0 = blockIdx.x * BN;

    const int w = tid >> 5, lane = tid & 31;
    const int gid = lane >> 2, tig = lane & 3;
    const int wm = w / WGN, wn = w % WGN;
    const int mBase = wm * MT * 16, nBase = wn * NT * 8;

    float acc[MT][NT][4];
    #pragma unroll
    for (int i = 0; i < MT; i++)
        #pragma unroll
        for (int j = 0; j < NT; j++)
            #pragma unroll
            for (int r = 0; r < 4; r++) acc[i][j][r] = 0.f;

    for (int k0 = 0; k0 < K; k0 += BK) {
        // ---- stage A tile [BM][BK] (row-major) ----
        #pragma unroll
        for (int l = 0; l < A_IT; l++) {
            int idx = (l * 256 + tid) * 4;
            int ar = idx / BK, ac = idx % BK;
            float4 v = *(const float4*)(Ab + (long long)(row0 + ar) * lda + k0 + ac);
            uint4 u = make_uint4(f2tf(v.x), f2tf(v.y), f2tf(v.z), f2tf(v.w));
            *(uint4*)&sA[ar * SAS + ac] = u;
        }
        // ---- stage B tile ----
        if (bMode == 0) {
            #pragma unroll
            for (int l = 0; l < B_IT; l++) {
                int idx = (l * 256 + tid) * 4;
                int br = idx / BN, bc = idx % BN;
                float4 v = *(const float4*)(Bb + (long long)(k0 + br) * ldb + col0 + bc);
                uint4 u = make_uint4(f2tf(v.x), f2tf(v.y), f2tf(v.z), f2tf(v.w));
                *(uint4*)&sB[br * SBS0 + bc] = u;
            }
        } else if (bMode == 1) {
            #pragma unroll
            for (int l = 0; l < B_IT; l++) {
                int idx = (l * 256 + tid) * 4;
                int br = idx / BN, bc = idx % BN;
                int n = col0 + bc; int h = n >> 6, dl = n & 63;
                float4 v = *(const float4*)(Bb + (long long)h * K * 64
                                            + (long long)(k0 + br) * 64 + dl);
                uint4 u = make_uint4(f2tf(v.x), f2tf(v.y), f2tf(v.z), f2tf(v.w));
                *(uint4*)&sB[br * SBS0 + bc] = u;
            }
        } else {
            #pragma unroll
            for (int l = 0; l < B_IT; l++) {
                int idx = (l * 256 + tid) * 4;
                int bn = idx / BK, bk = idx % BK;
                float4 v = *(const float4*)(Bb + (long long)(col0 + bn) * ldb + k0 + bk);
                uint4 u = make_uint4(f2tf(v.x), f2tf(v.y), f2tf(v.z), f2tf(v.w));
                *(uint4*)&sB[bn * SBS2 + bk] = u;
            }
        }
        __syncthreads();

        // ---- compute ----
        #pragma unroll
        for (int kk = 0; kk < BK; kk += 8) {
            uint32_t af[MT][4], bf[NT][2];
            #pragma unroll
            for (int mt = 0; mt < MT; mt++) {
                int m0 = mBase + mt * 16;
                af[mt][0] = sA[(m0 + gid)     * SAS + kk + tig];
                af[mt][1] = sA[(m0 + gid + 8) * SAS + kk + tig];
                af[mt][2] = sA[(m0 + gid)     * SAS + kk + tig + 4];
                af[mt][3] = sA[(m0 + gid + 8) * SAS + kk + tig + 4];
            }
            #pragma unroll
            for (int nt = 0; nt < NT; nt++) {
                int n0 = nBase + nt * 8;
                if (bMode == 2) {
                    bf[nt][0] = sB[(n0 + gid) * SBS2 + kk + tig];
                    bf[nt][1] = sB[(n0 + gid) * SBS2 + kk + tig + 4];
                } else {
                    bf[nt][0] = sB[(kk + tig)     * SBS0 + n0 + gid];
                    bf[nt][1] = sB[(kk + tig + 4) * SBS0 + n0 + gid];
                }
            }
            #pragma unroll
            for (int mt = 0; mt < MT; mt++)
                #pragma unroll
                for (int nt = 0; nt < NT; nt++)
                    mma_tf32(acc[mt][nt], af[mt], bf[nt]);
        }
        __syncthreads();
    }

    // ---- epilogue ----
    const int bz = z >> 4;   // batch when z = b*HN + h
    #pragma unroll
    for (int mt = 0; mt < MT; mt++) {
        #pragma unroll
        for (int h2 = 0; h2 < 2; h2++) {
            int m = row0 + mBase + mt * 16 + gid + h2 * 8;
            #pragma unroll
            for (int nt = 0; nt < NT; nt++) {
                #pragma unroll
                for (int j = 0; j < 2; j++) {
                    int n = col0 + nBase + nt * 8 + tig * 2 + j;
                    float vv = acc[mt][nt][h2 * 2 + j] * scale;
                    if (bias) vv += bias[n];
                    if (mA || mP) {
                        float mm = 0.f;
                        if (mA) mm += mA[(long long)m * N + n];
                        if (mP) mm += mP[bz * N + n];
                        if (isinf(mm) && mm < 0.f) vv = -INFINITY;
                    }
                    if (relu) vv = fmaxf(vv, 0.f);
                    if (cMode == 0) {
                        C[(long long)z * sCz + (long long)m * ldc + n] = vv;
                    } else if (cMode == 1) {
                        int nq = n + nOff;
                        int which = nq >> 10, h = (nq >> 6) & 15;
                        int b = m >> 9, s = m & 511, d = n & 63;
                        C[(long long)which * QKVOFF
                          + (((long long)(b * HN + h)) * SEQ + s) * DHD + d] = vv;
                    } else {
                        int h = z & 15;
                        C[((long long)(bz * SEQ + m)) * EDIM + h * DHD + n] = vv;
                    }
                }
            }
        }
    }
}

// ---------------- softmax over rows of length 512 ---------------------------
__global__ void softmax_k(float* __restrict__ p) {
    long long row = blockIdx.x;
    float* r = p + row * SEQ;
    int t = threadIdx.x;                  // 128 threads, 4 elems each
    float4 v = ((float4*)r)[t];
    float mx = fmaxf(fmaxf(v.x, v.y), fmaxf(v.z, v.w));
    mx = blockReduceMax(mx);
    float e0 = __expf(v.x - mx), e1 = __expf(v.y - mx);
    float e2 = __expf(v.z - mx), e3 = __expf(v.w - mx);
    float s = blockReduceSum(e0 + e1 + e2 + e3);
    float inv = 1.f / s;
    ((float4*)r)[t] = make_float4(e0 * inv, e1 * inv, e2 * inv, e3 * inv);
}

// ---------------- fused residual + LayerNorm (in-place) ---------------------
__global__ void ln_res_k(float* __restrict__ x, const float* __restrict__ d,
                         const float* __restrict__ g, const float* __restrict__ b)
{
    long long row = blockIdx.x;
    float* xr = x + row * EDIM;
    const float* dr = d + row * EDIM;
    int t = threadIdx.x;                  // 256 threads, 4 elems each
    float4 xv = ((float4*)xr)[t];
    float4 dv = ((const float4*)dr)[t];
    float v0 = xv.x + dv.x, v1 = xv.y + dv.y, v2 = xv.z + dv.z, v3 = xv.w + dv.w;
    float mean = blockReduceSum(v0 + v1 + v2 + v3) * (1.f / EDIM);
    float c0 = v0 - mean, c1 = v1 - mean, c2 = v2 - mean, c3 = v3 - mean;
    float var = blockReduceSum(c0 * c0 + c1 * c1 + c2 * c2 + c3 * c3) * (1.f / EDIM);
    float rstd = rsqrtf(var + 1e-5f);
    float4 gv = ((const float4*)g)[t];
    float4 bv = ((const float4*)b)[t];
    ((float4*)xr)[t] = make_float4(c0 * rstd * gv.x + bv.x, c1 * rstd * gv.y + bv.y,
                                   c2 * rstd * gv.z + bv.z, c3 * rstd * gv.w + bv.w);
}

// ---------------- host-side launch helpers ----------------------------------
// main: 128x128x16 tiles
template<int bMode>
static inline void gMain(const float* A, const float* Bm, const float* bias, float* C,
                         int M, int N, int K, int lda, int ldb, int ldc,
                         long long sAz, long long sBz, long long sCz, int nz,
                         int cMode, int relu, int nOff, float scale,
                         const float* mA, const float* mP)
{
    dim3 grid(N / 128, M / 128, nz);
    tmma_k<128, 128, 16, 2, 4, 4, 4, bMode><<<grid, 256>>>(
        A, Bm, bias, C, M, N, K, lda, ldb, ldc, sAz, sBz, sCz,
        cMode, relu, nOff, scale, mA, mP);
}
// 64x128x16 tiles (for N=1024 GEMMs -> 256 blocks)
template<int bMode>
static inline void gTall(const float* A, const float* Bm, const float* bias, float* C,
                         int M, int N, int K, int lda, int ldb, int ldc,
                         int cMode, int relu, int nOff, float scale)
{
    dim3 grid(N / 128, M / 64, 1);
    tmma_k<64, 128, 16, 2, 4, 2, 4, bMode><<<grid, 256>>>(
        A, Bm, bias, C, M, N, K, lda, ldb, ldc, 0, 0, 0,
        cMode, relu, nOff, scale, nullptr, nullptr);
}
// 128x64x32 tiles (PV)
static inline void gPV(const float* A, const float* Bm, float* C,
                       int M, int N, int K, int lda, int ldb,
                       long long sAz, long long sBz, int nz)
{
    dim3 grid(N / 64, M / 128, nz);
    tmma_k<128, 64, 32, 4, 2, 2, 4, 0><<<grid, 256>>>(
        A, Bm, nullptr, C, M, N, K, lda, ldb, 0, sAz, sBz, 0,
        2, 0, 0, 1.f, nullptr, nullptr);
}

// attention core after q/k/v are in g_qkv
static void attn_core(float* qkv, float* p, float* t1, float* t2,
                      const float* wo, const float* bo,
                      const float* mA, const float* mP)
{
    float* q = qkv;
    float* k = qkv + QKVOFF;
    float* v = qkv + 2 * QKVOFF;
    // scores = Q K^T / 8 (+ masks)
    gMain<2>(q, k, nullptr, p, SEQ, SEQ, DHD, DHD, DHD, SEQ,
             (long long)SEQ * DHD, (long long)SEQ * DHD, (long long)SEQ * SEQ, NBH,
             0, 0, 0, 0.125f, mA, mP);
    softmax_k<<<NBH * SEQ, 128>>>(p);
    // out = P V -> head-concat t1
    gPV(p, v, t1, SEQ, DHD, SEQ, SEQ, DHD,
        (long long)SEQ * SEQ, (long long)SEQ * DHD, NBH);
    // output projection + bias -> t2
    gTall<0>(t1, wo, bo, t2, NROWS, EDIM, EDIM, EDIM, EDIM, EDIM, 0, 0, 0, 1.f);
}

static void ffn_block(float* x, const float* w1, const float* b1,
                      const float* w2, const float* b2,
                      const float* lg, const float* lb, float* ff, float* t2)
{
    gMain<0>(x, w1, b1, ff, NROWS, DFFD, EDIM, EDIM, DFFD, DFFD, 0, 0, 0, 1,
             0, 1, 0, 1.f, nullptr, nullptr);
    gTall<0>(ff, w2, b2, t2, NROWS, EDIM, DFFD, DFFD, EDIM, EDIM, 0, 0, 0, 1.f);
    ln_res_k<<<NROWS, 256>>>(x, t2, lg, lb);
}

// ---------------- entry -----------------------------------------------------
extern "C" void kernel_launch(void* const* d_in, const int* in_sizes, int n_in,
                              void* d_out, int out_size)
{
    const float* src      = (const float*)d_in[0];
    const float* tgt      = (const float*)d_in[1];
    const float* src_mask = (const float*)d_in[2];
    const float* tgt_mask = (const float*)d_in[3];
    const float* src_pad  = (const float*)d_in[4];
    const float* tgt_pad  = (const float*)d_in[5];
    const float* enc_wqkv = (const float*)d_in[6];
    const float* enc_wo   = (const float*)d_in[7];
    const float* enc_bo   = (const float*)d_in[8];
    const float* enc_w1   = (const float*)d_in[9];
    const float* enc_b1   = (const float*)d_in[10];
    const float* enc_w2   = (const float*)d_in[11];
    const float* enc_b2   = (const float*)d_in[12];
    const float* enc_lg   = (const float*)d_in[13];
    const float* enc_lb   = (const float*)d_in[14];
    const float* dqkv_s   = (const float*)d_in[15];
    const float* dwo_s    = (const float*)d_in[16];
    const float* dbo_s    = (const float*)d_in[17];
    const float* dqkv_c   = (const float*)d_in[18];
    const float* dwo_c    = (const float*)d_in[19];
    const float* dbo_c    = (const float*)d_in[20];
    const float* dw1      = (const float*)d_in[21];
    const float* db1      = (const float*)d_in[22];
    const float* dw2      = (const float*)d_in[23];
    const float* db2      = (const float*)d_in[24];
    const float* dlg      = (const float*)d_in[25];
    const float* dlb      = (const float*)d_in[26];

    float *x, *y, *qkv, *p, *t1, *t2, *ff;
    cudaGetSymbolAddress((void**)&x,   g_x);
    cudaGetSymbolAddress((void**)&y,   g_y);
    cudaGetSymbolAddress((void**)&qkv, g_qkv);
    cudaGetSymbolAddress((void**)&p,   g_p);
    cudaGetSymbolAddress((void**)&t1,  g_t1);
    cudaGetSymbolAddress((void**)&t2,  g_t2);
    cudaGetSymbolAddress((void**)&ff,  g_ff);

    dim3 tg(SEQ, NB);
    reorder_k<<<tg, 256>>>(src, x, 1);
    reorder_k<<<tg, 256>>>(tgt, y, 1);

    const long long WL = (long long)3 * HN * EDIM * DHD;  // per-layer wqkv slab
    const long long WS = (long long)HN * EDIM * DHD;      // one of q/k/v

    for (int l = 0; l < NLE; l++) {
        // fused QKV projection: N = 3072 over (3,H,E,DH) slab
        gMain<1>(x, enc_wqkv + l * WL, nullptr, qkv, NROWS, 3 * EDIM, EDIM,
                 EDIM, 0, 0, 0, 0, 0, 1, 1, 0, 0, 1.f, nullptr, nullptr);
        attn_core(qkv, p, t1, t2,
                  enc_wo + (long long)l * EDIM * EDIM, enc_bo + l * EDIM,
                  src_mask, src_pad);
        ln_res_k<<<NROWS, 256>>>(x, t2, enc_lg + (l * 2 + 0) * EDIM, enc_lb + (l * 2 + 0) * EDIM);
        ffn_block(x, enc_w1 + (long long)l * EDIM * DFFD, enc_b1 + l * DFFD,
                  enc_w2 + (long long)l * DFFD * EDIM, enc_b2 + l * EDIM,
                  enc_lg + (l * 2 + 1) * EDIM, enc_lb + (l * 2 + 1) * EDIM, ff, t2);
    }

    for (int l = 0; l < NLD; l++) {
        // decoder self-attention (causal + pad mask)
        gMain<1>(y, dqkv_s + l * WL, nullptr, qkv, NROWS, 3 * EDIM, EDIM,
                 EDIM, 0, 0, 0, 0, 0, 1, 1, 0, 0, 1.f, nullptr, nullptr);
        attn_core(qkv, p, t1, t2,
                  dwo_s + (long long)l * EDIM * EDIM, dbo_s + l * EDIM,
                  tgt_mask, tgt_pad);
        ln_res_k<<<NROWS, 256>>>(y, t2, dlg + (l * 3 + 0) * EDIM, dlb + (l * 3 + 0) * EDIM);

        // cross-attention: Q from y, K/V from encoder output x
        gTall<1>(y, dqkv_c + l * WL, nullptr, qkv, NROWS, EDIM, EDIM,
                 EDIM, 0, 0, 1, 0, 0, 1.f);                       // Q (nOff=0)
        gMain<1>(x, dqkv_c + l * WL + WS, nullptr, qkv, NROWS, 2 * EDIM, EDIM,
                 EDIM, 0, 0, 0, 0, 0, 1, 1, 0, 1024, 1.f, nullptr, nullptr);  // K,V
        attn_core(qkv, p, t1, t2,
                  dwo_c + (long long)l * EDIM * EDIM, dbo_c + l * EDIM,
                  nullptr, src_pad);
        ln_res_k<<<NROWS, 256>>>(y, t2, dlg + (l * 3 + 1) * EDIM, dlb + (l * 3 + 1) * EDIM);

        // FFN
        ffn_block(y, dw1 + (long long)l * EDIM * DFFD, db1 + l * DFFD,
                  dw2 + (long long)l * DFFD * EDIM, db2 + l * EDIM,
                  dlg + (l * 3 + 2) * EDIM, dlb + (l * 3 + 2) * EDIM, ff, t2);
    }

    reorder_k<<<tg, 256>>>(y, (float*)d_out, 0);
}

// round 6
// speedup vs baseline: 3.7340x; 1.1294x over previous
#include <cuda_runtime.h>
#include <math.h>
#include <stdint.h>

// Problem constants
#define EDIM 1024
#define HN   16
#define DHD  64
#define DFFD 4096
#define NLE  4
#define NLD  4
#define NB   4
#define SEQ  512
#define NROWS (NB*SEQ)     // 2048
#define NBH   (NB*HN)      // 64
#define QKVOFF (NBH*SEQ*DHD)   // one q/k/v slab: 64*512*64 = 2M floats

// ---------------- scratch (static device globals; no allocations) ----------
__device__ float g_x  [NB*SEQ*EDIM];
__device__ float g_y  [NB*SEQ*EDIM];
__device__ float g_qkv[3*QKVOFF];                 // q|k|v, each (B,H,S,DH)
__device__ float g_p  [(long long)NBH*SEQ*SEQ];   // scores (B,H,S,T)
__device__ float g_t1 [NB*SEQ*EDIM];
__device__ float g_t2 [NB*SEQ*EDIM];
__device__ float g_ff [NB*SEQ*DFFD];

// ---------------- small helpers ---------------------------------------------
__device__ __forceinline__ uint32_t f2tf(float x) {
    uint32_t r; asm("cvt.rna.tf32.f32 %0, %1;" : "=r"(r) : "f"(x)); return r;
}
__device__ __forceinline__ uint4 cvt4(float4 v) {
    return make_uint4(f2tf(v.x), f2tf(v.y), f2tf(v.z), f2tf(v.w));
}
__device__ __forceinline__ void mma_tf32(float* c, const uint32_t* a, const uint32_t* b) {
    asm volatile("mma.sync.aligned.m16n8k8.row.col.f32.tf32.tf32.f32 "
                 "{%0,%1,%2,%3},{%4,%5,%6,%7},{%8,%9},{%0,%1,%2,%3};"
                 : "+f"(c[0]), "+f"(c[1]), "+f"(c[2]), "+f"(c[3])
                 : "r"(a[0]), "r"(a[1]), "r"(a[2]), "r"(a[3]), "r"(b[0]), "r"(b[1]));
}

__device__ __forceinline__ float blockReduceSum(float v) {
    __shared__ float sh[32];
    int lane = threadIdx.x & 31, w = threadIdx.x >> 5, nw = blockDim.x >> 5;
    #pragma unroll
    for (int o = 16; o; o >>= 1) v += __shfl_xor_sync(0xffffffffu, v, o);
    if (lane == 0) sh[w] = v;
    __syncthreads();
    if (w == 0) {
        float t = (lane < nw) ? sh[lane] : 0.f;
        #pragma unroll
        for (int o = 16; o; o >>= 1) t += __shfl_xor_sync(0xffffffffu, t, o);
        if (lane == 0) sh[0] = t;
    }
    __syncthreads();
    float r = sh[0]; __syncthreads(); return r;
}
__device__ __forceinline__ float blockReduceMax(float v) {
    __shared__ float sh[32];
    int lane = threadIdx.x & 31, w = threadIdx.x >> 5, nw = blockDim.x >> 5;
    #pragma unroll
    for (int o = 16; o; o >>= 1) v = fmaxf(v, __shfl_xor_sync(0xffffffffu, v, o));
    if (lane == 0) sh[w] = v;
    __syncthreads();
    if (w == 0) {
        float t = (lane < nw) ? sh[lane] : -INFINITY;
        #pragma unroll
        for (int o = 16; o; o >>= 1) t = fmaxf(t, __shfl_xor_sync(0xffffffffu, t, o));
        if (lane == 0) sh[0] = t;
    }
    __syncthreads();
    float r = sh[0]; __syncthreads(); return r;
}

// ---------------- layout swap (S,B,E) <-> (B,S,E) ---------------------------
__global__ void reorder_k(const float* __restrict__ in, float* __restrict__ out, int toBS) {
    int s = blockIdx.x, b = blockIdx.y;
    long long r_sb = ((long long)s * NB + b) * EDIM;
    long long r_bs = ((long long)b * SEQ + s) * EDIM;
    const float4* src = (const float4*)(in  + (toBS ? r_sb : r_bs));
    float4*       dst = (float4*)      (out + (toBS ? r_bs : r_sb));
    for (int i = threadIdx.x; i < EDIM / 4; i += blockDim.x) dst[i] = src[i];
}

// ---------------- TF32 tensor-core GEMM, double-buffered --------------------
// bMode (template): 0 = B row-major [k*ldb + n]
//                   1 = head-sliced weight: addr = (n>>6)*K*64 + k*64 + (n&63)
//                   2 = B transposed row-major [n*ldb + k]
// cMode (runtime):  0 = C[z*sCz + m*ldc + n]
//                   1 = qkv scatter with nOff into unified (3,B,H,S,DH) buffer
//                   2 = head concat: z=(b,h) -> ((b*SEQ+m))*EDIM + h*DHD + n
// epilogue: *scale, +bias[n], -inf mask (mA[m*N+n] + mP[bz*N+n] == -inf), relu
template<int BM, int BN, int BK, int WGM, int WGN, int MT, int NT, int bMode>
__global__ __launch_bounds__(256, 2)
void tmma_k(const float* __restrict__ A, const float* __restrict__ Bm,
            const float* __restrict__ bias, float* __restrict__ C,
            int M, int N, int K, int lda, int ldb, int ldc,
            long long sAz, long long sBz, long long sCz,
            int cMode, int relu, int nOff, float scale,
            const float* __restrict__ mA, const float* __restrict__ mP)
{
    constexpr int SAS  = BK + 4;   // sA stride (m-major rows)
    constexpr int SBS0 = BN + 8;   // sB stride for [k][n] layout
    constexpr int SBS2 = BK + 4;   // sB stride for [n][k] layout
    constexpr int SB_SZ = (BK * SBS0 > BN * SBS2) ? BK * SBS0 : BN * SBS2;
    constexpr int A_IT = (BM * BK) / 1024;
    constexpr int B_IT = (BK * BN) / 1024;

    __shared__ uint32_t sA[2][BM * SAS];
    __shared__ uint32_t sB[2][SB_SZ];

    const int z = blockIdx.z;
    const float* Ab = A  + (long long)z * sAz;
    const float* Bb = Bm + (long long)z * sBz;
    const int tid = threadIdx.x;
    const int row0 = blockIdx.y * BM, col0 = blockIdx.x * BN;

    const int w = tid >> 5, lane = tid & 31;
    const int gid = lane >> 2, tig = lane & 3;
    const int wm = w / WGN, wn = w % WGN;
    const int mBase = wm * MT * 16, nBase = wn * NT * 8;

    // per-thread constant staging coordinates
    int ar[A_IT], ac[A_IT];
    #pragma unroll
    for (int l = 0; l < A_IT; l++) {
        int idx = (l * 256 + tid) * 4;
        ar[l] = idx / BK; ac[l] = idx % BK;
    }
    int br[B_IT], bc[B_IT];               // meaning depends on bMode
    const float* bptr[B_IT];              // k-invariant base pointer
    #pragma unroll
    for (int l = 0; l < B_IT; l++) {
        int idx = (l * 256 + tid) * 4;
        if (bMode == 2) {
            br[l] = idx / BK; bc[l] = idx % BK;   // br=n, bc=k
            bptr[l] = Bb + (long long)(col0 + br[l]) * ldb + bc[l];
        } else {
            br[l] = idx / BN; bc[l] = idx % BN;   // br=k, bc=n
            if (bMode == 1) {
                int n = col0 + bc[l]; int h = n >> 6, dl = n & 63;
                bptr[l] = Bb + (long long)h * K * 64 + (long long)br[l] * 64 + dl;
            } else {
                bptr[l] = Bb + (long long)br[l] * ldb + col0 + bc[l];
            }
        }
    }
    // per-k-step pointer increments
    const long long aStep = BK;
    const long long bStep = (bMode == 0) ? (long long)BK * ldb
                          : (bMode == 1) ? (long long)BK * 64
                                         : (long long)BK;

    float acc[MT][NT][4];
    #pragma unroll
    for (int i = 0; i < MT; i++)
        #pragma unroll
        for (int j = 0; j < NT; j++)
            #pragma unroll
            for (int r = 0; r < 4; r++) acc[i][j][r] = 0.f;

    const int nit = K / BK;

    // ---- prologue: stage tile 0 into buffer 0 ----
    {
        #pragma unroll
        for (int l = 0; l < A_IT; l++) {
            float4 v = *(const float4*)(Ab + (long long)(row0 + ar[l]) * lda + ac[l]);
            *(uint4*)&sA[0][ar[l] * SAS + ac[l]] = cvt4(v);
        }
        #pragma unroll
        for (int l = 0; l < B_IT; l++) {
            float4 v = *(const float4*)bptr[l];
            if (bMode == 2) *(uint4*)&sB[0][br[l] * SBS2 + bc[l]] = cvt4(v);
            else            *(uint4*)&sB[0][br[l] * SBS0 + bc[l]] = cvt4(v);
        }
    }
    __syncthreads();

    for (int it = 0; it < nit; it++) {
        const int cur = it & 1;
        const bool pf = (it + 1 < nit);

        // ---- issue prefetch LDGs for tile it+1 ----
        float4 pa[A_IT], pb[B_IT];
        if (pf) {
            long long k1 = (long long)(it + 1) * aStep;
            #pragma unroll
            for (int l = 0; l < A_IT; l++)
                pa[l] = *(const float4*)(Ab + (long long)(row0 + ar[l]) * lda + k1 + ac[l]);
            long long kb = (long long)(it + 1) * bStep;
            #pragma unroll
            for (int l = 0; l < B_IT; l++)
                pb[l] = *(const float4*)(bptr[l] + kb);
        }

        // ---- compute on tile it ----
        #pragma unroll
        for (int kk = 0; kk < BK; kk += 8) {
            uint32_t af[MT][4], bf[NT][2];
            #pragma unroll
            for (int mt = 0; mt < MT; mt++) {
                int m0 = mBase + mt * 16;
                af[mt][0] = sA[cur][(m0 + gid)     * SAS + kk + tig];
                af[mt][1] = sA[cur][(m0 + gid + 8) * SAS + kk + tig];
                af[mt][2] = sA[cur][(m0 + gid)     * SAS + kk + tig + 4];
                af[mt][3] = sA[cur][(m0 + gid + 8) * SAS + kk + tig + 4];
            }
            #pragma unroll
            for (int nt = 0; nt < NT; nt++) {
                int n0 = nBase + nt * 8;
                if (bMode == 2) {
                    bf[nt][0] = sB[cur][(n0 + gid) * SBS2 + kk + tig];
                    bf[nt][1] = sB[cur][(n0 + gid) * SBS2 + kk + tig + 4];
                } else {
                    bf[nt][0] = sB[cur][(kk + tig)     * SBS0 + n0 + gid];
                    bf[nt][1] = sB[cur][(kk + tig + 4) * SBS0 + n0 + gid];
                }
            }
            #pragma unroll
            for (int mt = 0; mt < MT; mt++)
                #pragma unroll
                for (int nt = 0; nt < NT; nt++)
                    mma_tf32(acc[mt][nt], af[mt], bf[nt]);
        }

        // ---- store prefetched tile into other buffer ----
        if (pf) {
            const int nxt = cur ^ 1;
            #pragma unroll
            for (int l = 0; l < A_IT; l++)
                *(uint4*)&sA[nxt][ar[l] * SAS + ac[l]] = cvt4(pa[l]);
            #pragma unroll
            for (int l = 0; l < B_IT; l++) {
                if (bMode == 2) *(uint4*)&sB[nxt][br[l] * SBS2 + bc[l]] = cvt4(pb[l]);
                else            *(uint4*)&sB[nxt][br[l] * SBS0 + bc[l]] = cvt4(pb[l]);
            }
        }
        __syncthreads();
    }

    // ---- epilogue ----
    const int bz = z >> 4;   // batch when z = b*HN + h
    #pragma unroll
    for (int mt = 0; mt < MT; mt++) {
        #pragma unroll
        for (int h2 = 0; h2 < 2; h2++) {
            int m = row0 + mBase + mt * 16 + gid + h2 * 8;
            #pragma unroll
            for (int nt = 0; nt < NT; nt++) {
                #pragma unroll
                for (int j = 0; j < 2; j++) {
                    int n = col0 + nBase + nt * 8 + tig * 2 + j;
                    float vv = acc[mt][nt][h2 * 2 + j] * scale;
                    if (bias) vv += bias[n];
                    if (mA || mP) {
                        float mm = 0.f;
                        if (mA) mm += mA[(long long)m * N + n];
                        if (mP) mm += mP[bz * N + n];
                        if (isinf(mm) && mm < 0.f) vv = -INFINITY;
                    }
                    if (relu) vv = fmaxf(vv, 0.f);
                    if (cMode == 0) {
                        C[(long long)z * sCz + (long long)m * ldc + n] = vv;
                    } else if (cMode == 1) {
                        int nq = n + nOff;
                        int which = nq >> 10, h = (nq >> 6) & 15;
                        int b = m >> 9, s = m & 511, d = n & 63;
                        C[(long long)which * QKVOFF
                          + (((long long)(b * HN + h)) * SEQ + s) * DHD + d] = vv;
                    } else {
                        int h = z & 15;
                        C[((long long)(bz * SEQ + m)) * EDIM + h * DHD + n] = vv;
                    }
                }
            }
        }
    }
}

// ---------------- softmax over rows of length 512 ---------------------------
__global__ void softmax_k(float* __restrict__ p) {
    long long row = blockIdx.x;
    float* r = p + row * SEQ;
    int t = threadIdx.x;                  // 128 threads, 4 elems each
    float4 v = ((float4*)r)[t];
    float mx = fmaxf(fmaxf(v.x, v.y), fmaxf(v.z, v.w));
    mx = blockReduceMax(mx);
    float e0 = __expf(v.x - mx), e1 = __expf(v.y - mx);
    float e2 = __expf(v.z - mx), e3 = __expf(v.w - mx);
    float s = blockReduceSum(e0 + e1 + e2 + e3);
    float inv = 1.f / s;
    ((float4*)r)[t] = make_float4(e0 * inv, e1 * inv, e2 * inv, e3 * inv);
}

// ---------------- fused residual + LayerNorm (in-place) ---------------------
__global__ void ln_res_k(float* __restrict__ x, const float* __restrict__ d,
                         const float* __restrict__ g, const float* __restrict__ b)
{
    long long row = blockIdx.x;
    float* xr = x + row * EDIM;
    const float* dr = d + row * EDIM;
    int t = threadIdx.x;                  // 256 threads, 4 elems each
    float4 xv = ((float4*)xr)[t];
    float4 dv = ((const float4*)dr)[t];
    float v0 = xv.x + dv.x, v1 = xv.y + dv.y, v2 = xv.z + dv.z, v3 = xv.w + dv.w;
    float mean = blockReduceSum(v0 + v1 + v2 + v3) * (1.f / EDIM);
    float c0 = v0 - mean, c1 = v1 - mean, c2 = v2 - mean, c3 = v3 - mean;
    float var = blockReduceSum(c0 * c0 + c1 * c1 + c2 * c2 + c3 * c3) * (1.f / EDIM);
    float rstd = rsqrtf(var + 1e-5f);
    float4 gv = ((const float4*)g)[t];
    float4 bv = ((const float4*)b)[t];
    ((float4*)xr)[t] = make_float4(c0 * rstd * gv.x + bv.x, c1 * rstd * gv.y + bv.y,
                                   c2 * rstd * gv.z + bv.z, c3 * rstd * gv.w + bv.w);
}

// ---------------- host-side launch helpers ----------------------------------
// main: 128x128x16 tiles
template<int bMode>
static inline void gMain(const float* A, const float* Bm, const float* bias, float* C,
                         int M, int N, int K, int lda, int ldb, int ldc,
                         long long sAz, long long sBz, long long sCz, int nz,
                         int cMode, int relu, int nOff, float scale,
                         const float* mA, const float* mP)
{
    dim3 grid(N / 128, M / 128, nz);
    tmma_k<128, 128, 16, 2, 4, 4, 4, bMode><<<grid, 256>>>(
        A, Bm, bias, C, M, N, K, lda, ldb, ldc, sAz, sBz, sCz,
        cMode, relu, nOff, scale, mA, mP);
}
// 64x128x16 tiles (for N=1024 GEMMs -> 256 blocks)
template<int bMode>
static inline void gTall(const float* A, const float* Bm, const float* bias, float* C,
                         int M, int N, int K, int lda, int ldb, int ldc,
                         int cMode, int relu, int nOff, float scale)
{
    dim3 grid(N / 128, M / 64, 1);
    tmma_k<64, 128, 16, 2, 4, 2, 4, bMode><<<grid, 256>>>(
        A, Bm, bias, C, M, N, K, lda, ldb, ldc, 0, 0, 0,
        cMode, relu, nOff, scale, nullptr, nullptr);
}
// 128x64x16 tiles (PV)
static inline void gPV(const float* A, const float* Bm, float* C,
                       int M, int N, int K, int lda, int ldb,
                       long long sAz, long long sBz, int nz)
{
    dim3 grid(N / 64, M / 128, nz);
    tmma_k<128, 64, 16, 4, 2, 2, 4, 0><<<grid, 256>>>(
        A, Bm, nullptr, C, M, N, K, lda, ldb, 0, sAz, sBz, 0,
        2, 0, 0, 1.f, nullptr, nullptr);
}

// attention core after q/k/v are in g_qkv
static void attn_core(float* qkv, float* p, float* t1, float* t2,
                      const float* wo, const float* bo,
                      const float* mA, const float* mP)
{
    float* q = qkv;
    float* k = qkv + QKVOFF;
    float* v = qkv + 2 * QKVOFF;
    // scores = Q K^T / 8 (+ masks)
    gMain<2>(q, k, nullptr, p, SEQ, SEQ, DHD, DHD, DHD, SEQ,
             (long long)SEQ * DHD, (long long)SEQ * DHD, (long long)SEQ * SEQ, NBH,
             0, 0, 0, 0.125f, mA, mP);
    softmax_k<<<NBH * SEQ, 128>>>(p);
    // out = P V -> head-concat t1
    gPV(p, v, t1, SEQ, DHD, SEQ, SEQ, DHD,
        (long long)SEQ * SEQ, (long long)SEQ * DHD, NBH);
    // output projection + bias -> t2
    gTall<0>(t1, wo, bo, t2, NROWS, EDIM, EDIM, EDIM, EDIM, EDIM, 0, 0, 0, 1.f);
}

static void ffn_block(float* x, const float* w1, const float* b1,
                      const float* w2, const float* b2,
                      const float* lg, const float* lb, float* ff, float* t2)
{
    gMain<0>(x, w1, b1, ff, NROWS, DFFD, EDIM, EDIM, DFFD, DFFD, 0, 0, 0, 1,
             0, 1, 0, 1.f, nullptr, nullptr);
    gTall<0>(ff, w2, b2, t2, NROWS, EDIM, DFFD, DFFD, EDIM, EDIM, 0, 0, 0, 1.f);
    ln_res_k<<<NROWS, 256>>>(x, t2, lg, lb);
}

// ---------------- entry -----------------------------------------------------
extern "C" void kernel_launch(void* const* d_in, const int* in_sizes, int n_in,
                              void* d_out, int out_size)
{
    const float* src      = (const float*)d_in[0];
    const float* tgt      = (const float*)d_in[1];
    const float* src_mask = (const float*)d_in[2];
    const float* tgt_mask = (const float*)d_in[3];
    const float* src_pad  = (const float*)d_in[4];
    const float* tgt_pad  = (const float*)d_in[5];
    const float* enc_wqkv = (const float*)d_in[6];
    const float* enc_wo   = (const float*)d_in[7];
    const float* enc_bo   = (const float*)d_in[8];
    const float* enc_w1   = (const float*)d_in[9];
    const float* enc_b1   = (const float*)d_in[10];
    const float* enc_w2   = (const float*)d_in[11];
    const float* enc_b2   = (const float*)d_in[12];
    const float* enc_lg   = (const float*)d_in[13];
    const float* enc_lb   = (const float*)d_in[14];
    const float* dqkv_s   = (const float*)d_in[15];
    const float* dwo_s    = (const float*)d_in[16];
    const float* dbo_s    = (const float*)d_in[17];
    const float* dqkv_c   = (const float*)d_in[18];
    const float* dwo_c    = (const float*)d_in[19];
    const float* dbo_c    = (const float*)d_in[20];
    const float* dw1      = (const float*)d_in[21];
    const float* db1      = (const float*)d_in[22];
    const float* dw2      = (const float*)d_in[23];
    const float* db2      = (const float*)d_in[24];
    const float* dlg      = (const float*)d_in[25];
    const float* dlb      = (const float*)d_in[26];

    float *x, *y, *qkv, *p, *t1, *t2, *ff;
    cudaGetSymbolAddress((void**)&x,   g_x);
    cudaGetSymbolAddress((void**)&y,   g_y);
    cudaGetSymbolAddress((void**)&qkv, g_qkv);
    cudaGetSymbolAddress((void**)&p,   g_p);
    cudaGetSymbolAddress((void**)&t1,  g_t1);
    cudaGetSymbolAddress((void**)&t2,  g_t2);
    cudaGetSymbolAddress((void**)&ff,  g_ff);

    dim3 tg(SEQ, NB);
    reorder_k<<<tg, 256>>>(src, x, 1);
    reorder_k<<<tg, 256>>>(tgt, y, 1);

    const long long WL = (long long)3 * HN * EDIM * DHD;  // per-layer wqkv slab
    const long long WS = (long long)HN * EDIM * DHD;      // one of q/k/v

    for (int l = 0; l < NLE; l++) {
        // fused QKV projection: N = 3072 over (3,H,E,DH) slab
        gMain<1>(x, enc_wqkv + l * WL, nullptr, qkv, NROWS, 3 * EDIM, EDIM,
                 EDIM, 0, 0, 0, 0, 0, 1, 1, 0, 0, 1.f, nullptr, nullptr);
        attn_core(qkv, p, t1, t2,
                  enc_wo + (long long)l * EDIM * EDIM, enc_bo + l * EDIM,
                  src_mask, src_pad);
        ln_res_k<<<NROWS, 256>>>(x, t2, enc_lg + (l * 2 + 0) * EDIM, enc_lb + (l * 2 + 0) * EDIM);
        ffn_block(x, enc_w1 + (long long)l * EDIM * DFFD, enc_b1 + l * DFFD,
                  enc_w2 + (long long)l * DFFD * EDIM, enc_b2 + l * EDIM,
                  enc_lg + (l * 2 + 1) * EDIM, enc_lb + (l * 2 + 1) * EDIM, ff, t2);
    }

    for (int l = 0; l < NLD; l++) {
        // decoder self-attention (causal + pad mask)
        gMain<1>(y, dqkv_s + l * WL, nullptr, qkv, NROWS, 3 * EDIM, EDIM,
                 EDIM, 0, 0, 0, 0, 0, 1, 1, 0, 0, 1.f, nullptr, nullptr);
        attn_core(qkv, p, t1, t2,
                  dwo_s + (long long)l * EDIM * EDIM, dbo_s + l * EDIM,
                  tgt_mask, tgt_pad);
        ln_res_k<<<NROWS, 256>>>(y, t2, dlg + (l * 3 + 0) * EDIM, dlb + (l * 3 + 0) * EDIM);

        // cross-attention: Q from y, K/V from encoder output x
        gTall<1>(y, dqkv_c + l * WL, nullptr, qkv, NROWS, EDIM, EDIM,
                 EDIM, 0, 0, 1, 0, 0, 1.f);                       // Q (nOff=0)
        gMain<1>(x, dqkv_c + l * WL + WS, nullptr, qkv, NROWS, 2 * EDIM, EDIM,
                 EDIM, 0, 0, 0, 0, 0, 1, 1, 0, 1024, 1.f, nullptr, nullptr);  // K,V
        attn_core(qkv, p, t1, t2,
                  dwo_c + (long long)l * EDIM * EDIM, dbo_c + l * EDIM,
                  nullptr, src_pad);
        ln_res_k<<<NROWS, 256>>>(y, t2, dlg + (l * 3 + 1) * EDIM, dlb + (l * 3 + 1) * EDIM);

        // FFN
        ffn_block(y, dw1 + (long long)l * EDIM * DFFD, db1 + l * DFFD,
                  dw2 + (long long)l * DFFD * EDIM, db2 + l * EDIM,
                  dlg + (l * 3 + 2) * EDIM, dlb + (l * 3 + 2) * EDIM, ff, t2);
    }

    reorder_k<<<tg, 256>>>(y, (float*)d_out, 0);
}

// round 9
// speedup vs baseline: 4.4672x; 1.1964x over previous
#include <cuda_runtime.h>
#include <math.h>
#include <stdint.h>

// Problem constants
#define EDIM 1024
#define HN   16
#define DHD  64
#define DFFD 4096
#define NLE  4
#define NLD  4
#define NB   4
#define SEQ  512
#define NROWS (NB*SEQ)     // 2048
#define NBH   (NB*HN)      // 64
#define QKVOFF (NBH*SEQ*DHD)   // one q/k/v slab: 64*512*64 = 2M floats

// ---------------- scratch (static device globals; no allocations) ----------
__device__ float g_x  [NB*SEQ*EDIM];
__device__ float g_y  [NB*SEQ*EDIM];
__device__ float g_qkv[3*QKVOFF];                 // q|k|v, each (B,H,S,DH)
__device__ float g_t1 [NB*SEQ*EDIM];
__device__ float g_t2 [NB*SEQ*EDIM];
__device__ float g_ff [NB*SEQ*DFFD];

// ---------------- small helpers ---------------------------------------------
__device__ __forceinline__ uint32_t f2tf(float x) {
    uint32_t r; asm("cvt.rna.tf32.f32 %0, %1;" : "=r"(r) : "f"(x)); return r;
}
__device__ __forceinline__ uint4 cvt4(float4 v) {
    return make_uint4(f2tf(v.x), f2tf(v.y), f2tf(v.z), f2tf(v.w));
}
__device__ __forceinline__ void mma_tf32(float* c, const uint32_t* a, const uint32_t* b) {
    asm volatile("mma.sync.aligned.m16n8k8.row.col.f32.tf32.tf32.f32 "
                 "{%0,%1,%2,%3},{%4,%5,%6,%7},{%8,%9},{%0,%1,%2,%3};"
                 : "+f"(c[0]), "+f"(c[1]), "+f"(c[2]), "+f"(c[3])
                 : "r"(a[0]), "r"(a[1]), "r"(a[2]), "r"(a[3]), "r"(b[0]), "r"(b[1]));
}

__device__ __forceinline__ float blockReduceSum(float v) {
    __shared__ float sh[32];
    int lane = threadIdx.x & 31, w = threadIdx.x >> 5, nw = blockDim.x >> 5;
    #pragma unroll
    for (int o = 16; o; o >>= 1) v += __shfl_xor_sync(0xffffffffu, v, o);
    if (lane == 0) sh[w] = v;
    __syncthreads();
    if (w == 0) {
        float t = (lane < nw) ? sh[lane] : 0.f;
        #pragma unroll
        for (int o = 16; o; o >>= 1) t += __shfl_xor_sync(0xffffffffu, t, o);
        if (lane == 0) sh[0] = t;
    }
    __syncthreads();
    float r = sh[0]; __syncthreads(); return r;
}

// ---------------- layout swap (S,B,E) <-> (B,S,E) ---------------------------
__global__ void reorder_k(const float* __restrict__ in, float* __restrict__ out, int toBS) {
    int s = blockIdx.x, b = blockIdx.y;
    long long r_sb = ((long long)s * NB + b) * EDIM;
    long long r_bs = ((long long)b * SEQ + s) * EDIM;
    const float4* src = (const float4*)(in  + (toBS ? r_sb : r_bs));
    float4*       dst = (float4*)      (out + (toBS ? r_bs : r_sb));
    for (int i = threadIdx.x; i < EDIM / 4; i += blockDim.x) dst[i] = src[i];
}

// ---------------- TF32 tensor-core GEMM, double-buffered --------------------
// bMode: 0 = B row-major; 1 = head-sliced weight (n>>6)*K*64 + k*64 + (n&63)
// cMode: 0 = C[z*sCz + m*ldc + n]; 1 = qkv scatter (+nOff) into (3,B,H,S,DH)
template<int BM, int BN, int BK, int WGM, int WGN, int MT, int NT, int bMode>
__global__ __launch_bounds__(256, 2)
void tmma_k(const float* __restrict__ A, const float* __restrict__ Bm,
            const float* __restrict__ bias, float* __restrict__ C,
            int M, int N, int K, int lda, int ldb, int ldc,
            long long sAz, long long sBz, long long sCz,
            int cMode, int relu, int nOff, float scale)
{
    constexpr int SAS  = BK + 4;
    constexpr int SBS0 = BN + 8;
    constexpr int A_IT = (BM * BK) / 1024;
    constexpr int B_IT = (BK * BN) / 1024;

    __shared__ uint32_t sA[2][BM * SAS];
    __shared__ uint32_t sB[2][BK * SBS0];

    const int z = blockIdx.z;
    const float* Ab = A  + (long long)z * sAz;
    const float* Bb = Bm + (long long)z * sBz;
    const int tid = threadIdx.x;
    const int row0 = blockIdx.y * BM, col0 = blockIdx.x * BN;

    const int w = tid >> 5, lane = tid & 31;
    const int gid = lane >> 2, tig = lane & 3;
    const int wm = w / WGN, wn = w % WGN;
    const int mBase = wm * MT * 16, nBase = wn * NT * 8;

    int ar[A_IT], ac[A_IT];
    #pragma unroll
    for (int l = 0; l < A_IT; l++) {
        int idx = (l * 256 + tid) * 4;
        ar[l] = idx / BK; ac[l] = idx % BK;
    }
    int br[B_IT], bc[B_IT];
    const float* bptr[B_IT];
    #pragma unroll
    for (int l = 0; l < B_IT; l++) {
        int idx = (l * 256 + tid) * 4;
        br[l] = idx / BN; bc[l] = idx % BN;
        if (bMode == 1) {
            int n = col0 + bc[l]; int h = n >> 6, dl = n & 63;
            bptr[l] = Bb + (long long)h * K * 64 + (long long)br[l] * 64 + dl;
        } else {
            bptr[l] = Bb + (long long)br[l] * ldb + col0 + bc[l];
        }
    }
    const long long bStep = (bMode == 0) ? (long long)BK * ldb : (long long)BK * 64;

    float acc[MT][NT][4];
    #pragma unroll
    for (int i = 0; i < MT; i++)
        #pragma unroll
        for (int j = 0; j < NT; j++)
            #pragma unroll
            for (int r = 0; r < 4; r++) acc[i][j][r] = 0.f;

    const int nit = K / BK;

    {
        #pragma unroll
        for (int l = 0; l < A_IT; l++) {
            float4 v = *(const float4*)(Ab + (long long)(row0 + ar[l]) * lda + ac[l]);
            *(uint4*)&sA[0][ar[l] * SAS + ac[l]] = cvt4(v);
        }
        #pragma unroll
        for (int l = 0; l < B_IT; l++) {
            float4 v = *(const float4*)bptr[l];
            *(uint4*)&sB[0][br[l] * SBS0 + bc[l]] = cvt4(v);
        }
    }
    __syncthreads();

    for (int it = 0; it < nit; it++) {
        const int cur = it & 1;
        const bool pf = (it + 1 < nit);

        float4 pa[A_IT], pb[B_IT];
        if (pf) {
            long long k1 = (long long)(it + 1) * BK;
            #pragma unroll
            for (int l = 0; l < A_IT; l++)
                pa[l] = *(const float4*)(Ab + (long long)(row0 + ar[l]) * lda + k1 + ac[l]);
            long long kb = (long long)(it + 1) * bStep;
            #pragma unroll
            for (int l = 0; l < B_IT; l++)
                pb[l] = *(const float4*)(bptr[l] + kb);
        }

        #pragma unroll
        for (int kk = 0; kk < BK; kk += 8) {
            uint32_t af[MT][4], bf[NT][2];
            #pragma unroll
            for (int mt = 0; mt < MT; mt++) {
                int m0 = mBase + mt * 16;
                af[mt][0] = sA[cur][(m0 + gid)     * SAS + kk + tig];
                af[mt][1] = sA[cur][(m0 + gid + 8) * SAS + kk + tig];
                af[mt][2] = sA[cur][(m0 + gid)     * SAS + kk + tig + 4];
                af[mt][3] = sA[cur][(m0 + gid + 8) * SAS + kk + tig + 4];
            }
            #pragma unroll
            for (int nt = 0; nt < NT; nt++) {
                int n0 = nBase + nt * 8;
                bf[nt][0] = sB[cur][(kk + tig)     * SBS0 + n0 + gid];
                bf[nt][1] = sB[cur][(kk + tig + 4) * SBS0 + n0 + gid];
            }
            #pragma unroll
            for (int mt = 0; mt < MT; mt++)
                #pragma unroll
                for (int nt = 0; nt < NT; nt++)
                    mma_tf32(acc[mt][nt], af[mt], bf[nt]);
        }

        if (pf) {
            const int nxt = cur ^ 1;
            #pragma unroll
            for (int l = 0; l < A_IT; l++)
                *(uint4*)&sA[nxt][ar[l] * SAS + ac[l]] = cvt4(pa[l]);
            #pragma unroll
            for (int l = 0; l < B_IT; l++)
                *(uint4*)&sB[nxt][br[l] * SBS0 + bc[l]] = cvt4(pb[l]);
        }
        __syncthreads();
    }

    #pragma unroll
    for (int mt = 0; mt < MT; mt++) {
        #pragma unroll
        for (int h2 = 0; h2 < 2; h2++) {
            int m = row0 + mBase + mt * 16 + gid + h2 * 8;
            #pragma unroll
            for (int nt = 0; nt < NT; nt++) {
                #pragma unroll
                for (int j = 0; j < 2; j++) {
                    int n = col0 + nBase + nt * 8 + tig * 2 + j;
                    float vv = acc[mt][nt][h2 * 2 + j] * scale;
                    if (bias) vv += bias[n];
                    if (relu) vv = fmaxf(vv, 0.f);
                    if (cMode == 0) {
                        C[(long long)z * sCz + (long long)m * ldc + n] = vv;
                    } else {
                        int nq = n + nOff;
                        int which = nq >> 10, h = (nq >> 6) & 15;
                        int b = m >> 9, s = m & 511, d = n & 63;
                        C[(long long)which * QKVOFF
                          + (((long long)(b * HN + h)) * SEQ + s) * DHD + d] = vv;
                    }
                }
            }
        }
    }
}

// ---------------- fused flash attention --------------------------------------
// grid (SEQ/128, NBH), 256 threads. q/k/v: (B,H,S,64) slabs. out: head-concat
// (B,S,E). pad: (B,S) additive mask (0 / -inf) or nullptr. CAUSAL: analytic
// causal mask (col > row -> -inf).
#define SKS 68   // sK stride (words)
#define SVS 72   // sV stride (words)
template<int CAUSAL>
__global__ __launch_bounds__(256, 2)
void flash_k(const float* __restrict__ q, const float* __restrict__ k,
             const float* __restrict__ v, const float* __restrict__ pad,
             float* __restrict__ out)
{
    __shared__ uint32_t sK[64 * SKS];
    __shared__ uint32_t sV[64 * SVS];
    __shared__ float sPad[64];

    const int tid  = threadIdx.x;
    const int w    = tid >> 5, lane = tid & 31;
    const int gid  = lane >> 2, tig = lane & 3;
    const int bh   = blockIdx.y;
    const int b    = bh >> 4, h = bh & 15;
    const int qbase = blockIdx.x * 128 + w * 16;
    const int row0 = qbase + gid, row1 = row0 + 8;

    // Q fragments (scaled by 1/8), kept in registers
    uint32_t qf[8][4];
    {
        const float* qp = q + ((long long)bh * SEQ) * DHD;
        #pragma unroll
        for (int kk = 0; kk < 8; kk++) {
            qf[kk][0] = f2tf(0.125f * qp[(long long)row0 * DHD + kk * 8 + tig]);
            qf[kk][1] = f2tf(0.125f * qp[(long long)row1 * DHD + kk * 8 + tig]);
            qf[kk][2] = f2tf(0.125f * qp[(long long)row0 * DHD + kk * 8 + tig + 4]);
            qf[kk][3] = f2tf(0.125f * qp[(long long)row1 * DHD + kk * 8 + tig + 4]);
        }
    }

    float oacc[8][4];
    #pragma unroll
    for (int nt = 0; nt < 8; nt++)
        #pragma unroll
        for (int r = 0; r < 4; r++) oacc[nt][r] = 0.f;
    float m0 = -INFINITY, m1 = -INFINITY, l0 = 0.f, l1 = 0.f;

    const int Tend = CAUSAL ? (blockIdx.x * 128 + 128) : SEQ;

    for (int t0 = 0; t0 < Tend; t0 += 64) {
        // ---- stage K and V tiles (converted to tf32) ----
        {
            const float* kp = k + ((long long)bh * SEQ + t0) * DHD;
            const float* vp = v + ((long long)bh * SEQ + t0) * DHD;
            #pragma unroll
            for (int i = 0; i < 4; i++) {
                int e = (i * 256 + tid) * 4;
                int t = e >> 6, d = e & 63;
                float4 kv = *(const float4*)(kp + (long long)t * DHD + d);
                *(uint4*)&sK[t * SKS + d] = cvt4(kv);
                float4 vv = *(const float4*)(vp + (long long)t * DHD + d);
                *(uint4*)&sV[t * SVS + d] = cvt4(vv);
            }
            if (tid < 64) sPad[tid] = pad ? pad[b * SEQ + t0 + tid] : 0.f;
        }
        __syncthreads();

        // ---- scores S = Qs @ K^T  (16 x 64 per warp) ----
        float s[8][4];
        #pragma unroll
        for (int nt = 0; nt < 8; nt++)
            #pragma unroll
            for (int r = 0; r < 4; r++) s[nt][r] = 0.f;
        #pragma unroll
        for (int kk = 0; kk < 8; kk++) {
            #pragma unroll
            for (int nt = 0; nt < 8; nt++) {
                uint32_t bf[2];
                bf[0] = sK[(nt * 8 + gid) * SKS + kk * 8 + tig];
                bf[1] = sK[(nt * 8 + gid) * SKS + kk * 8 + tig + 4];
                mma_tf32(s[nt], qf[kk], bf);
            }
        }

        // ---- masks ----
        #pragma unroll
        for (int nt = 0; nt < 8; nt++) {
            int c0 = nt * 8 + 2 * tig, c1 = c0 + 1;
            float p0 = sPad[c0], p1 = sPad[c1];
            s[nt][0] += p0; s[nt][1] += p1;
            s[nt][2] += p0; s[nt][3] += p1;
            if (CAUSAL) {
                int tc0 = t0 + c0, tc1 = t0 + c1;
                if (tc0 > row0) s[nt][0] = -INFINITY;
                if (tc1 > row0) s[nt][1] = -INFINITY;
                if (tc0 > row1) s[nt][2] = -INFINITY;
                if (tc1 > row1) s[nt][3] = -INFINITY;
            }
        }

        // ---- online softmax ----
        float mt0 = -INFINITY, mt1 = -INFINITY;
        #pragma unroll
        for (int nt = 0; nt < 8; nt++) {
            mt0 = fmaxf(mt0, fmaxf(s[nt][0], s[nt][1]));
            mt1 = fmaxf(mt1, fmaxf(s[nt][2], s[nt][3]));
        }
        mt0 = fmaxf(mt0, __shfl_xor_sync(0xffffffffu, mt0, 1));
        mt0 = fmaxf(mt0, __shfl_xor_sync(0xffffffffu, mt0, 2));
        mt1 = fmaxf(mt1, __shfl_xor_sync(0xffffffffu, mt1, 1));
        mt1 = fmaxf(mt1, __shfl_xor_sync(0xffffffffu, mt1, 2));
        float mn0 = fmaxf(m0, mt0), mn1 = fmaxf(m1, mt1);
        float sc0 = __expf(m0 - mn0), sc1 = __expf(m1 - mn1);

        float rs0 = 0.f, rs1 = 0.f;
        #pragma unroll
        for (int nt = 0; nt < 8; nt++) {
            s[nt][0] = __expf(s[nt][0] - mn0);
            s[nt][1] = __expf(s[nt][1] - mn0);
            s[nt][2] = __expf(s[nt][2] - mn1);
            s[nt][3] = __expf(s[nt][3] - mn1);
            rs0 += s[nt][0] + s[nt][1];
            rs1 += s[nt][2] + s[nt][3];
        }
        rs0 += __shfl_xor_sync(0xffffffffu, rs0, 1);
        rs0 += __shfl_xor_sync(0xffffffffu, rs0, 2);
        rs1 += __shfl_xor_sync(0xffffffffu, rs1, 1);
        rs1 += __shfl_xor_sync(0xffffffffu, rs1, 2);
        l0 = l0 * sc0 + rs0;
        l1 = l1 * sc1 + rs1;
        m0 = mn0; m1 = mn1;
        #pragma unroll
        for (int nt = 0; nt < 8; nt++) {
            oacc[nt][0] *= sc0; oacc[nt][1] *= sc0;
            oacc[nt][2] *= sc1; oacc[nt][3] *= sc1;
        }

        // ---- O += P @ V ; P converted C-frag -> A-frag via quad shuffles ----
        const int qlane = lane & ~3;
        const int sl0 = qlane | (tig >> 1);
        const int sl1 = sl0 + 2;
        #pragma unroll
        for (int kk = 0; kk < 8; kk++) {
            float u00 = __shfl_sync(0xffffffffu, s[kk][0], sl0);
            float u01 = __shfl_sync(0xffffffffu, s[kk][1], sl0);
            float u02 = __shfl_sync(0xffffffffu, s[kk][0], sl1);
            float u03 = __shfl_sync(0xffffffffu, s[kk][1], sl1);
            float u10 = __shfl_sync(0xffffffffu, s[kk][2], sl0);
            float u11 = __shfl_sync(0xffffffffu, s[kk][3], sl0);
            float u12 = __shfl_sync(0xffffffffu, s[kk][2], sl1);
            float u13 = __shfl_sync(0xffffffffu, s[kk][3], sl1);
            uint32_t af[4];
            af[0] = f2tf((tig & 1) ? u01 : u00);
            af[1] = f2tf((tig & 1) ? u11 : u10);
            af[2] = f2tf((tig & 1) ? u03 : u02);
            af[3] = f2tf((tig & 1) ? u13 : u12);
            #pragma unroll
            for (int nt = 0; nt < 8; nt++) {
                uint32_t bf[2];
                bf[0] = sV[(kk * 8 + tig)     * SVS + nt * 8 + gid];
                bf[1] = sV[(kk * 8 + tig + 4) * SVS + nt * 8 + gid];
                mma_tf32(oacc[nt], af, bf);
            }
        }
        __syncthreads();
    }

    // ---- write head-concat output ----
    float inv0 = 1.f / l0, inv1 = 1.f / l1;
    float* o0 = out + ((long long)(b * SEQ + row0)) * EDIM + h * DHD;
    float* o1 = out + ((long long)(b * SEQ + row1)) * EDIM + h * DHD;
    #pragma unroll
    for (int nt = 0; nt < 8; nt++) {
        int c = nt * 8 + 2 * tig;
        *(float2*)(o0 + c) = make_float2(oacc[nt][0] * inv0, oacc[nt][1] * inv0);
        *(float2*)(o1 + c) = make_float2(oacc[nt][2] * inv1, oacc[nt][3] * inv1);
    }
}

// ---------------- fused residual + LayerNorm (in-place) ---------------------
__global__ void ln_res_k(float* __restrict__ x, const float* __restrict__ d,
                         const float* __restrict__ g, const float* __restrict__ b)
{
    long long row = blockIdx.x;
    float* xr = x + row * EDIM;
    const float* dr = d + row * EDIM;
    int t = threadIdx.x;
    float4 xv = ((float4*)xr)[t];
    float4 dv = ((const float4*)dr)[t];
    float v0 = xv.x + dv.x, v1 = xv.y + dv.y, v2 = xv.z + dv.z, v3 = xv.w + dv.w;
    float mean = blockReduceSum(v0 + v1 + v2 + v3) * (1.f / EDIM);
    float c0 = v0 - mean, c1 = v1 - mean, c2 = v2 - mean, c3 = v3 - mean;
    float var = blockReduceSum(c0 * c0 + c1 * c1 + c2 * c2 + c3 * c3) * (1.f / EDIM);
    float rstd = rsqrtf(var + 1e-5f);
    float4 gv = ((const float4*)g)[t];
    float4 bv = ((const float4*)b)[t];
    ((float4*)xr)[t] = make_float4(c0 * rstd * gv.x + bv.x, c1 * rstd * gv.y + bv.y,
                                   c2 * rstd * gv.z + bv.z, c3 * rstd * gv.w + bv.w);
}

// ---------------- host-side launch helpers ----------------------------------
template<int bMode>
static inline void gMain(const float* A, const float* Bm, const float* bias, float* C,
                         int M, int N, int K, int lda, int ldb, int ldc,
                         int cMode, int relu, int nOff, float scale)
{
    dim3 grid(N / 128, M / 128, 1);
    tmma_k<128, 128, 16, 2, 4, 4, 4, bMode><<<grid, 256>>>(
        A, Bm, bias, C, M, N, K, lda, ldb, ldc, 0, 0, 0, cMode, relu, nOff, scale);
}
template<int bMode>
static inline void gTall(const float* A, const float* Bm, const float* bias, float* C,
                         int M, int N, int K, int lda, int ldb, int ldc,
                         int cMode, int relu, int nOff, float scale)
{
    dim3 grid(N / 128, M / 64, 1);
    tmma_k<64, 128, 16, 2, 4, 2, 4, bMode><<<grid, 256>>>(
        A, Bm, bias, C, M, N, K, lda, ldb, ldc, 0, 0, 0, cMode, relu, nOff, scale);
}

// attention core after q/k/v are in g_qkv
static void attn_core(float* qkv, float* t1, float* t2,
                      const float* wo, const float* bo,
                      const float* pad, int causal)
{
    float* q = qkv;
    float* k = qkv + QKVOFF;
    float* v = qkv + 2 * QKVOFF;
    dim3 fg(SEQ / 128, NBH);
    if (causal) flash_k<1><<<fg, 256>>>(q, k, v, pad, t1);
    else        flash_k<0><<<fg, 256>>>(q, k, v, pad, t1);
    gTall<0>(t1, wo, bo, t2, NROWS, EDIM, EDIM, EDIM, EDIM, EDIM, 0, 0, 0, 1.f);
}

static void ffn_block(float* x, const float* w1, const float* b1,
                      const float* w2, const float* b2,
                      const float* lg, const float* lb, float* ff, float* t2)
{
    gMain<0>(x, w1, b1, ff, NROWS, DFFD, EDIM, EDIM, DFFD, DFFD, 0, 1, 0, 1.f);
    gTall<0>(ff, w2, b2, t2, NROWS, EDIM, DFFD, DFFD, EDIM, EDIM, 0, 0, 0, 1.f);
    ln_res_k<<<NROWS, 256>>>(x, t2, lg, lb);
}

// ---------------- entry -----------------------------------------------------
extern "C" void kernel_launch(void* const* d_in, const int* in_sizes, int n_in,
                              void* d_out, int out_size)
{
    const float* src      = (const float*)d_in[0];
    const float* tgt      = (const float*)d_in[1];
    const float* src_pad  = (const float*)d_in[4];
    const float* tgt_pad  = (const float*)d_in[5];
    const float* enc_wqkv = (const float*)d_in[6];
    const float* enc_wo   = (const float*)d_in[7];
    const float* enc_bo   = (const float*)d_in[8];
    const float* enc_w1   = (const float*)d_in[9];
    const float* enc_b1   = (const float*)d_in[10];
    const float* enc_w2   = (const float*)d_in[11];
    const float* enc_b2   = (const float*)d_in[12];
    const float* enc_lg   = (const float*)d_in[13];
    const float* enc_lb   = (const float*)d_in[14];
    const float* dqkv_s   = (const float*)d_in[15];
    const float* dwo_s    = (const float*)d_in[16];
    const float* dbo_s    = (const float*)d_in[17];
    const float* dqkv_c   = (const float*)d_in[18];
    const float* dwo_c    = (const float*)d_in[19];
    const float* dbo_c    = (const float*)d_in[20];
    const float* dw1      = (const float*)d_in[21];
    const float* db1      = (const float*)d_in[22];
    const float* dw2      = (const float*)d_in[23];
    const float* db2      = (const float*)d_in[24];
    const float* dlg      = (const float*)d_in[25];
    const float* dlb      = (const float*)d_in[26];

    float *x, *y, *qkv, *t1, *t2, *ff;
    cudaGetSymbolAddress((void**)&x,   g_x);
    cudaGetSymbolAddress((void**)&y,   g_y);
    cudaGetSymbolAddress((void**)&qkv, g_qkv);
    cudaGetSymbolAddress((void**)&t1,  g_t1);
    cudaGetSymbolAddress((void**)&t2,  g_t2);
    cudaGetSymbolAddress((void**)&ff,  g_ff);

    dim3 tg(SEQ, NB);
    reorder_k<<<tg, 256>>>(src, x, 1);
    reorder_k<<<tg, 256>>>(tgt, y, 1);

    const long long WL = (long long)3 * HN * EDIM * DHD;
    const long long WS = (long long)HN * EDIM * DHD;

    for (int l = 0; l < NLE; l++) {
        gMain<1>(x, enc_wqkv + l * WL, nullptr, qkv, NROWS, 3 * EDIM, EDIM,
                 EDIM, 0, 0, 1, 0, 0, 1.f);
        attn_core(qkv, t1, t2,
                  enc_wo + (long long)l * EDIM * EDIM, enc_bo + l * EDIM,
                  src_pad, 0);
        ln_res_k<<<NROWS, 256>>>(x, t2, enc_lg + (l * 2 + 0) * EDIM, enc_lb + (l * 2 + 0) * EDIM);
        ffn_block(x, enc_w1 + (long long)l * EDIM * DFFD, enc_b1 + l * DFFD,
                  enc_w2 + (long long)l * DFFD * EDIM, enc_b2 + l * EDIM,
                  enc_lg + (l * 2 + 1) * EDIM, enc_lb + (l * 2 + 1) * EDIM, ff, t2);
    }

    for (int l = 0; l < NLD; l++) {
        // decoder self-attention (analytic causal + pad)
        gMain<1>(y, dqkv_s + l * WL, nullptr, qkv, NROWS, 3 * EDIM, EDIM,
                 EDIM, 0, 0, 1, 0, 0, 1.f);
        attn_core(qkv, t1, t2,
                  dwo_s + (long long)l * EDIM * EDIM, dbo_s + l * EDIM,
                  tgt_pad, 1);
        ln_res_k<<<NROWS, 256>>>(y, t2, dlg + (l * 3 + 0) * EDIM, dlb + (l * 3 + 0) * EDIM);

        // cross-attention: Q from y, K/V from encoder output x
        gTall<1>(y, dqkv_c + l * WL, nullptr, qkv, NROWS, EDIM, EDIM,
                 EDIM, 0, 0, 1, 0, 0, 1.f);
        gMain<1>(x, dqkv_c + l * WL + WS, nullptr, qkv, NROWS, 2 * EDIM, EDIM,
                 EDIM, 0, 0, 1, 0, 1024, 1.f);
        attn_core(qkv, t1, t2,
                  dwo_c + (long long)l * EDIM * EDIM, dbo_c + l * EDIM,
                  src_pad, 0);
        ln_res_k<<<NROWS, 256>>>(y, t2, dlg + (l * 3 + 1) * EDIM, dlb + (l * 3 + 1) * EDIM);

        ffn_block(y, dw1 + (long long)l * EDIM * DFFD, db1 + l * DFFD,
                  dw2 + (long long)l * DFFD * EDIM, db2 + l * EDIM,
                  dlg + (l * 3 + 2) * EDIM, dlb + (l * 3 + 2) * EDIM, ff, t2);
    }

    reorder_k<<<tg, 256>>>(y, (float*)d_out, 0);
}

// round 11
// speedup vs baseline: 4.6662x; 1.0446x over previous
#include <cuda_runtime.h>
#include <math.h>
#include <stdint.h>

// Problem constants
#define EDIM 1024
#define HN   16
#define DHD  64
#define DFFD 4096
#define NLE  4
#define NLD  4
#define NB   4
#define SEQ  512
#define NROWS (NB*SEQ)     // 2048
#define NBH   (NB*HN)      // 64
#define QKVOFF (NBH*SEQ*DHD)   // one q/k/v slab: 64*512*64 = 2M floats

// ---------------- scratch (static device globals; no allocations) ----------
__device__ float g_x  [NB*SEQ*EDIM];
__device__ float g_y  [NB*SEQ*EDIM];
__device__ float g_qkv[3*QKVOFF];                 // q|k|v, each (B,H,S,DH)
__device__ float g_t1 [NB*SEQ*EDIM];
__device__ float g_t2 [NB*SEQ*EDIM];
__device__ float g_ff [NB*SEQ*DFFD];

// ---------------- small helpers ---------------------------------------------
__device__ __forceinline__ uint32_t f2tf(float x) {
    uint32_t r; asm("cvt.rna.tf32.f32 %0, %1;" : "=r"(r) : "f"(x)); return r;
}
__device__ __forceinline__ uint4 cvt4(float4 v) {
    return make_uint4(f2tf(v.x), f2tf(v.y), f2tf(v.z), f2tf(v.w));
}
__device__ __forceinline__ void mma_tf32(float* c, const uint32_t* a, const uint32_t* b) {
    asm volatile("mma.sync.aligned.m16n8k8.row.col.f32.tf32.tf32.f32 "
                 "{%0,%1,%2,%3},{%4,%5,%6,%7},{%8,%9},{%0,%1,%2,%3};"
                 : "+f"(c[0]), "+f"(c[1]), "+f"(c[2]), "+f"(c[3])
                 : "r"(a[0]), "r"(a[1]), "r"(a[2]), "r"(a[3]), "r"(b[0]), "r"(b[1]));
}
__device__ __forceinline__ void cp_async16(uint32_t dst, const void* src) {
    asm volatile("cp.async.cg.shared.global [%0], [%1], 16;\n" :: "r"(dst), "l"(src));
}
__device__ __forceinline__ void cp_async8(uint32_t dst, const void* src) {
    asm volatile("cp.async.ca.shared.global [%0], [%1], 8;\n" :: "r"(dst), "l"(src));
}
__device__ __forceinline__ void cp_commit() {
    asm volatile("cp.async.commit_group;\n");
}
template<int N>
__device__ __forceinline__ void cp_wait() {
    asm volatile("cp.async.wait_group %0;\n" :: "n"(N));
}

__device__ __forceinline__ float blockReduceSum(float v) {
    __shared__ float sh[32];
    int lane = threadIdx.x & 31, w = threadIdx.x >> 5, nw = blockDim.x >> 5;
    #pragma unroll
    for (int o = 16; o; o >>= 1) v += __shfl_xor_sync(0xffffffffu, v, o);
    if (lane == 0) sh[w] = v;
    __syncthreads();
    if (w == 0) {
        float t = (lane < nw) ? sh[lane] : 0.f;
        #pragma unroll
        for (int o = 16; o; o >>= 1) t += __shfl_xor_sync(0xffffffffu, t, o);
        if (lane == 0) sh[0] = t;
    }
    __syncthreads();
    float r = sh[0]; __syncthreads(); return r;
}

// ---------------- layout swap (S,B,E) <-> (B,S,E) ---------------------------
__global__ void reorder_k(const float* __restrict__ in, float* __restrict__ out, int toBS) {
    int s = blockIdx.x, b = blockIdx.y;
    long long r_sb = ((long long)s * NB + b) * EDIM;
    long long r_bs = ((long long)b * SEQ + s) * EDIM;
    const float4* src = (const float4*)(in  + (toBS ? r_sb : r_bs));
    float4*       dst = (float4*)      (out + (toBS ? r_bs : r_sb));
    for (int i = threadIdx.x; i < EDIM / 4; i += blockDim.x) dst[i] = src[i];
}

// ---------------- TF32 tensor-core GEMM, 4-stage cp.async pipeline ----------
// bMode: 0 = B row-major [k*ldb + n]; 1 = head-sliced weight (n>>6)*K*64+k*64+(n&63)
// cMode: 0 = C[m*ldc + n]; 1 = qkv scatter (+nOff) into unified (3,B,H,S,DH)
template<int BM, int BN, int BK, int STG, int WGN, int MT, int NT, int bMode>
__global__ __launch_bounds__(256, 2)
void tmma_k(const float* __restrict__ A, const float* __restrict__ Bm,
            const float* __restrict__ bias, float* __restrict__ C,
            int M, int N, int K, int lda, int ldb, int ldc,
            int cMode, int relu, int nOff, float scale)
{
    constexpr int SAS   = BK + 4;          // 12 words/row (bank-safe for gid stride)
    constexpr int SBS   = BN + 8;          // 136 words/row
    constexpr int A_PER = (BM * BK) / 256; // floats per thread per stage (4 or 2)
    constexpr int STG_A = BM * SAS;        // words per A stage
    constexpr int STG_B = BK * SBS;        // words per B stage

    __shared__ float sA[STG][STG_A];
    __shared__ float sB[STG][STG_B];

    const int tid = threadIdx.x;
    const int row0 = blockIdx.y * BM, col0 = blockIdx.x * BN;
    const int w = tid >> 5, lane = tid & 31;
    const int gid = lane >> 2, tig = lane & 3;
    const int wm = w / WGN, wn = w % WGN;
    const int mBase = wm * MT * 16, nBase = wn * NT * 8;

    // staging coordinates (constant per thread)
    const int arA = (tid * A_PER) / BK, acA = (tid * A_PER) % BK;
    const int brB = (tid * 4) / BN,    bcB = (tid * 4) % BN;
    const float* aSrc = A + (long long)(row0 + arA) * lda + acA;
    const float* bSrc;
    if (bMode == 1) {
        int n = col0 + bcB; int h = n >> 6, dl = n & 63;
        bSrc = Bm + (long long)h * K * 64 + (long long)brB * 64 + dl;
    } else {
        bSrc = Bm + (long long)brB * ldb + col0 + bcB;
    }
    const long long bStep = (bMode == 0) ? (long long)BK * ldb : (long long)BK * 64;

    const uint32_t sAu = (uint32_t)__cvta_generic_to_shared(&sA[0][0])
                       + (uint32_t)(arA * SAS + acA) * 4u;
    const uint32_t sBu = (uint32_t)__cvta_generic_to_shared(&sB[0][0])
                       + (uint32_t)(brB * SBS + bcB) * 4u;

    float acc[MT][NT][4];
    #pragma unroll
    for (int i = 0; i < MT; i++)
        #pragma unroll
        for (int j = 0; j < NT; j++)
            #pragma unroll
            for (int r = 0; r < 4; r++) acc[i][j][r] = 0.f;

    const int nit = K / BK;

    // ---- prologue: issue STG-1 stages ----
    #pragma unroll
    for (int s = 0; s < STG - 1; s++) {
        if (s < nit) {
            if (A_PER == 4) cp_async16(sAu + s * STG_A * 4, aSrc + s * BK);
            else            cp_async8 (sAu + s * STG_A * 4, aSrc + s * BK);
            cp_async16(sBu + s * STG_B * 4, bSrc + (long long)s * bStep);
        }
        cp_commit();
    }

    for (int it = 0; it < nit; it++) {
        cp_wait<STG - 2>();
        __syncthreads();

        const int buf = it % STG;
        const float* sAf = sA[buf];
        const float* sBf = sB[buf];

        uint32_t af[MT][4], bf[NT][2];
        #pragma unroll
        for (int mt = 0; mt < MT; mt++) {
            int m0 = mBase + mt * 16;
            af[mt][0] = f2tf(sAf[(m0 + gid)     * SAS + tig]);
            af[mt][1] = f2tf(sAf[(m0 + gid + 8) * SAS + tig]);
            af[mt][2] = f2tf(sAf[(m0 + gid)     * SAS + tig + 4]);
            af[mt][3] = f2tf(sAf[(m0 + gid + 8) * SAS + tig + 4]);
        }
        #pragma unroll
        for (int nt = 0; nt < NT; nt++) {
            int n0 = nBase + nt * 8;
            bf[nt][0] = f2tf(sBf[tig       * SBS + n0 + gid]);
            bf[nt][1] = f2tf(sBf[(tig + 4) * SBS + n0 + gid]);
        }
        #pragma unroll
        for (int mt = 0; mt < MT; mt++)
            #pragma unroll
            for (int nt = 0; nt < NT; nt++)
                mma_tf32(acc[mt][nt], af[mt], bf[nt]);

        // ---- issue stage it+STG-1 into the buffer consumed at it-1 ----
        const int nx = it + STG - 1;
        if (nx < nit) {
            const int nb = nx % STG;
            if (A_PER == 4) cp_async16(sAu + nb * STG_A * 4, aSrc + (long long)nx * BK);
            else            cp_async8 (sAu + nb * STG_A * 4, aSrc + (long long)nx * BK);
            cp_async16(sBu + nb * STG_B * 4, bSrc + (long long)nx * bStep);
        }
        cp_commit();
    }
    cp_wait<0>();   // drain before CTA exit (smem reuse hazard)

    // ---- epilogue (float2 stores; n pairs never cross a head boundary) ----
    #pragma unroll
    for (int mt = 0; mt < MT; mt++) {
        #pragma unroll
        for (int h2 = 0; h2 < 2; h2++) {
            int m = row0 + mBase + mt * 16 + gid + h2 * 8;
            #pragma unroll
            for (int nt = 0; nt < NT; nt++) {
                int n = col0 + nBase + nt * 8 + tig * 2;
                float v0 = acc[mt][nt][h2 * 2 + 0] * scale;
                float v1 = acc[mt][nt][h2 * 2 + 1] * scale;
                if (bias) { v0 += bias[n]; v1 += bias[n + 1]; }
                if (relu) { v0 = fmaxf(v0, 0.f); v1 = fmaxf(v1, 0.f); }
                if (cMode == 0) {
                    *(float2*)&C[(long long)m * ldc + n] = make_float2(v0, v1);
                } else {
                    int nq = n + nOff;
                    int which = nq >> 10, h = (nq >> 6) & 15;
                    int b = m >> 9, s = m & 511, d = n & 63;
                    *(float2*)&C[(long long)which * QKVOFF
                        + (((long long)(b * HN + h)) * SEQ + s) * DHD + d] = make_float2(v0, v1);
                }
            }
        }
    }
}

// ---------------- fused flash attention --------------------------------------
// grid (SEQ/128, NBH), 256 threads. q/k/v: (B,H,S,64) slabs. out: head-concat
// (B,S,E). pad: (B,S) additive mask (0 / -inf) or nullptr. CAUSAL: analytic.
#define SKS 68   // sK stride (words)
#define SVS 72   // sV stride (words)
template<int CAUSAL>
__global__ __launch_bounds__(256, 2)
void flash_k(const float* __restrict__ q, const float* __restrict__ k,
             const float* __restrict__ v, const float* __restrict__ pad,
             float* __restrict__ out)
{
    __shared__ uint32_t sK[64 * SKS];
    __shared__ uint32_t sV[64 * SVS];
    __shared__ float sPad[64];

    const int tid  = threadIdx.x;
    const int w    = tid >> 5, lane = tid & 31;
    const int gid  = lane >> 2, tig = lane & 3;
    const int bh   = blockIdx.y;
    const int b    = bh >> 4, h = bh & 15;
    const int qbase = blockIdx.x * 128 + w * 16;
    const int row0 = qbase + gid, row1 = row0 + 8;

    uint32_t qf[8][4];
    {
        const float* qp = q + ((long long)bh * SEQ) * DHD;
        #pragma unroll
        for (int kk = 0; kk < 8; kk++) {
            qf[kk][0] = f2tf(0.125f * qp[(long long)row0 * DHD + kk * 8 + tig]);
            qf[kk][1] = f2tf(0.125f * qp[(long long)row1 * DHD + kk * 8 + tig]);
            qf[kk][2] = f2tf(0.125f * qp[(long long)row0 * DHD + kk * 8 + tig + 4]);
            qf[kk][3] = f2tf(0.125f * qp[(long long)row1 * DHD + kk * 8 + tig + 4]);
        }
    }

    float oacc[8][4];
    #pragma unroll
    for (int nt = 0; nt < 8; nt++)
        #pragma unroll
        for (int r = 0; r < 4; r++) oacc[nt][r] = 0.f;
    float m0 = -INFINITY, m1 = -INFINITY, l0 = 0.f, l1 = 0.f;

    const int Tend = CAUSAL ? (blockIdx.x * 128 + 128) : SEQ;

    for (int t0 = 0; t0 < Tend; t0 += 64) {
        {
            const float* kp = k + ((long long)bh * SEQ + t0) * DHD;
            const float* vp = v + ((long long)bh * SEQ + t0) * DHD;
            #pragma unroll
            for (int i = 0; i < 4; i++) {
                int e = (i * 256 + tid) * 4;
                int t = e >> 6, d = e & 63;
                float4 kv = *(const float4*)(kp + (long long)t * DHD + d);
                *(uint4*)&sK[t * SKS + d] = cvt4(kv);
                float4 vv = *(const float4*)(vp + (long long)t * DHD + d);
                *(uint4*)&sV[t * SVS + d] = cvt4(vv);
            }
            if (tid < 64) sPad[tid] = pad ? pad[b * SEQ + t0 + tid] : 0.f;
        }
        __syncthreads();

        float s[8][4];
        #pragma unroll
        for (int nt = 0; nt < 8; nt++)
            #pragma unroll
            for (int r = 0; r < 4; r++) s[nt][r] = 0.f;
        #pragma unroll
        for (int kk = 0; kk < 8; kk++) {
            #pragma unroll
            for (int nt = 0; nt < 8; nt++) {
                uint32_t bf[2];
                bf[0] = sK[(nt * 8 + gid) * SKS + kk * 8 + tig];
                bf[1] = sK[(nt * 8 + gid) * SKS + kk * 8 + tig + 4];
                mma_tf32(s[nt], qf[kk], bf);
            }
        }

        #pragma unroll
        for (int nt = 0; nt < 8; nt++) {
            int c0 = nt * 8 + 2 * tig, c1 = c0 + 1;
            float p0 = sPad[c0], p1 = sPad[c1];
            s[nt][0] += p0; s[nt][1] += p1;
            s[nt][2] += p0; s[nt][3] += p1;
            if (CAUSAL) {
                int tc0 = t0 + c0, tc1 = t0 + c1;
                if (tc0 > row0) s[nt][0] = -INFINITY;
                if (tc1 > row0) s[nt][1] = -INFINITY;
                if (tc0 > row1) s[nt][2] = -INFINITY;
                if (tc1 > row1) s[nt][3] = -INFINITY;
            }
        }

        float mt0 = -INFINITY, mt1 = -INFINITY;
        #pragma unroll
        for (int nt = 0; nt < 8; nt++) {
            mt0 = fmaxf(mt0, fmaxf(s[nt][0], s[nt][1]));
            mt1 = fmaxf(mt1, fmaxf(s[nt][2], s[nt][3]));
        }
        mt0 = fmaxf(mt0, __shfl_xor_sync(0xffffffffu, mt0, 1));
        mt0 = fmaxf(mt0, __shfl_xor_sync(0xffffffffu, mt0, 2));
        mt1 = fmaxf(mt1, __shfl_xor_sync(0xffffffffu, mt1, 1));
        mt1 = fmaxf(mt1, __shfl_xor_sync(0xffffffffu, mt1, 2));
        float mn0 = fmaxf(m0, mt0), mn1 = fmaxf(m1, mt1);
        float sc0 = __expf(m0 - mn0), sc1 = __expf(m1 - mn1);

        float rs0 = 0.f, rs1 = 0.f;
        #pragma unroll
        for (int nt = 0; nt < 8; nt++) {
            s[nt][0] = __expf(s[nt][0] - mn0);
            s[nt][1] = __expf(s[nt][1] - mn0);
            s[nt][2] = __expf(s[nt][2] - mn1);
            s[nt][3] = __expf(s[nt][3] - mn1);
            rs0 += s[nt][0] + s[nt][1];
            rs1 += s[nt][2] + s[nt][3];
        }
        rs0 += __shfl_xor_sync(0xffffffffu, rs0, 1);
        rs0 += __shfl_xor_sync(0xffffffffu, rs0, 2);
        rs1 += __shfl_xor_sync(0xffffffffu, rs1, 1);
        rs1 += __shfl_xor_sync(0xffffffffu, rs1, 2);
        l0 = l0 * sc0 + rs0;
        l1 = l1 * sc1 + rs1;
        m0 = mn0; m1 = mn1;
        #pragma unroll
        for (int nt = 0; nt < 8; nt++) {
            oacc[nt][0] *= sc0; oacc[nt][1] *= sc0;
            oacc[nt][2] *= sc1; oacc[nt][3] *= sc1;
        }

        const int qlane = lane & ~3;
        const int sl0 = qlane | (tig >> 1);
        const int sl1 = sl0 + 2;
        #pragma unroll
        for (int kk = 0; kk < 8; kk++) {
            float u00 = __shfl_sync(0xffffffffu, s[kk][0], sl0);
            float u01 = __shfl_sync(0xffffffffu, s[kk][1], sl0);
            float u02 = __shfl_sync(0xffffffffu, s[kk][0], sl1);
            float u03 = __shfl_sync(0xffffffffu, s[kk][1], sl1);
            float u10 = __shfl_sync(0xffffffffu, s[kk][2], sl0);
            float u11 = __shfl_sync(0xffffffffu, s[kk][3], sl0);
            float u12 = __shfl_sync(0xffffffffu, s[kk][2], sl1);
            float u13 = __shfl_sync(0xffffffffu, s[kk][3], sl1);
            uint32_t af[4];
            af[0] = f2tf((tig & 1) ? u01 : u00);
            af[1] = f2tf((tig & 1) ? u11 : u10);
            af[2] = f2tf((tig & 1) ? u03 : u02);
            af[3] = f2tf((tig & 1) ? u13 : u12);
            #pragma unroll
            for (int nt = 0; nt < 8; nt++) {
                uint32_t bf[2];
                bf[0] = sV[(kk * 8 + tig)     * SVS + nt * 8 + gid];
                bf[1] = sV[(kk * 8 + tig + 4) * SVS + nt * 8 + gid];
                mma_tf32(oacc[nt], af, bf);
            }
        }
        __syncthreads();
    }

    float inv0 = 1.f / l0, inv1 = 1.f / l1;
    float* o0 = out + ((long long)(b * SEQ + row0)) * EDIM + h * DHD;
    float* o1 = out + ((long long)(b * SEQ + row1)) * EDIM + h * DHD;
    #pragma unroll
    for (int nt = 0; nt < 8; nt++) {
        int c = nt * 8 + 2 * tig;
        *(float2*)(o0 + c) = make_float2(oacc[nt][0] * inv0, oacc[nt][1] * inv0);
        *(float2*)(o1 + c) = make_float2(oacc[nt][2] * inv1, oacc[nt][3] * inv1);
    }
}

// ---------------- fused residual + LayerNorm (in-place) ---------------------
__global__ void ln_res_k(float* __restrict__ x, const float* __restrict__ d,
                         const float* __restrict__ g, const float* __restrict__ b)
{
    long long row = blockIdx.x;
    float* xr = x + row * EDIM;
    const float* dr = d + row * EDIM;
    int t = threadIdx.x;
    float4 xv = ((float4*)xr)[t];
    float4 dv = ((const float4*)dr)[t];
    float v0 = xv.x + dv.x, v1 = xv.y + dv.y, v2 = xv.z + dv.z, v3 = xv.w + dv.w;
    float mean = blockReduceSum(v0 + v1 + v2 + v3) * (1.f / EDIM);
    float c0 = v0 - mean, c1 = v1 - mean, c2 = v2 - mean, c3 = v3 - mean;
    float var = blockReduceSum(c0 * c0 + c1 * c1 + c2 * c2 + c3 * c3) * (1.f / EDIM);
    float rstd = rsqrtf(var + 1e-5f);
    float4 gv = ((const float4*)g)[t];
    float4 bv = ((const float4*)b)[t];
    ((float4*)xr)[t] = make_float4(c0 * rstd * gv.x + bv.x, c1 * rstd * gv.y + bv.y,
                                   c2 * rstd * gv.z + bv.z, c3 * rstd * gv.w + bv.w);
}

// ---------------- host-side launch helpers ----------------------------------
template<int bMode>
static inline void gMain(const float* A, const float* Bm, const float* bias, float* C,
                         int M, int N, int K, int lda, int ldb, int ldc,
                         int cMode, int relu, int nOff, float scale)
{
    dim3 grid(N / 128, M / 128, 1);
    tmma_k<128, 128, 8, 4, 4, 4, 4, bMode><<<grid, 256>>>(
        A, Bm, bias, C, M, N, K, lda, ldb, ldc, cMode, relu, nOff, scale);
}
template<int bMode>
static inline void gTall(const float* A, const float* Bm, const float* bias, float* C,
                         int M, int N, int K, int lda, int ldb, int ldc,
                         int cMode, int relu, int nOff, float scale)
{
    dim3 grid(N / 128, M / 64, 1);
    tmma_k<64, 128, 8, 4, 4, 2, 4, bMode><<<grid, 256>>>(
        A, Bm, bias, C, M, N, K, lda, ldb, ldc, cMode, relu, nOff, scale);
}

// attention core after q/k/v are in g_qkv
static void attn_core(float* qkv, float* t1, float* t2,
                      const float* wo, const float* bo,
                      const float* pad, int causal)
{
    float* q = qkv;
    float* k = qkv + QKVOFF;
    float* v = qkv + 2 * QKVOFF;
    dim3 fg(SEQ / 128, NBH);
    if (causal) flash_k<1><<<fg, 256>>>(q, k, v, pad, t1);
    else        flash_k<0><<<fg, 256>>>(q, k, v, pad, t1);
    gTall<0>(t1, wo, bo, t2, NROWS, EDIM, EDIM, EDIM, EDIM, EDIM, 0, 0, 0, 1.f);
}

static void ffn_block(float* x, const float* w1, const float* b1,
                      const float* w2, const float* b2,
                      const float* lg, const float* lb, float* ff, float* t2)
{
    gMain<0>(x, w1, b1, ff, NROWS, DFFD, EDIM, EDIM, DFFD, DFFD, 0, 1, 0, 1.f);
    gTall<0>(ff, w2, b2, t2, NROWS, EDIM, DFFD, DFFD, EDIM, EDIM, 0, 0, 0, 1.f);
    ln_res_k<<<NROWS, 256>>>(x, t2, lg, lb);
}

// ---------------- entry -----------------------------------------------------
extern "C" void kernel_launch(void* const* d_in, const int* in_sizes, int n_in,
                              void* d_out, int out_size)
{
    const float* src      = (const float*)d_in[0];
    const float* tgt      = (const float*)d_in[1];
    const float* src_pad  = (const float*)d_in[4];
    const float* tgt_pad  = (const float*)d_in[5];
    const float* enc_wqkv = (const float*)d_in[6];
    const float* enc_wo   = (const float*)d_in[7];
    const float* enc_bo   = (const float*)d_in[8];
    const float* enc_w1   = (const float*)d_in[9];
    const float* enc_b1   = (const float*)d_in[10];
    const float* enc_w2   = (const float*)d_in[11];
    const float* enc_b2   = (const float*)d_in[12];
    const float* enc_lg   = (const float*)d_in[13];
    const float* enc_lb   = (const float*)d_in[14];
    const float* dqkv_s   = (const float*)d_in[15];
    const float* dwo_s    = (const float*)d_in[16];
    const float* dbo_s    = (const float*)d_in[17];
    const float* dqkv_c   = (const float*)d_in[18];
    const float* dwo_c    = (const float*)d_in[19];
    const float* dbo_c    = (const float*)d_in[20];
    const float* dw1      = (const float*)d_in[21];
    const float* db1      = (const float*)d_in[22];
    const float* dw2      = (const float*)d_in[23];
    const float* db2      = (const float*)d_in[24];
    const float* dlg      = (const float*)d_in[25];
    const float* dlb      = (const float*)d_in[26];

    float *x, *y, *qkv, *t1, *t2, *ff;
    cudaGetSymbolAddress((void**)&x,   g_x);
    cudaGetSymbolAddress((void**)&y,   g_y);
    cudaGetSymbolAddress((void**)&qkv, g_qkv);
    cudaGetSymbolAddress((void**)&t1,  g_t1);
    cudaGetSymbolAddress((void**)&t2,  g_t2);
    cudaGetSymbolAddress((void**)&ff,  g_ff);

    dim3 tg(SEQ, NB);
    reorder_k<<<tg, 256>>>(src, x, 1);
    reorder_k<<<tg, 256>>>(tgt, y, 1);

    const long long WL = (long long)3 * HN * EDIM * DHD;
    const long long WS = (long long)HN * EDIM * DHD;

    for (int l = 0; l < NLE; l++) {
        gMain<1>(x, enc_wqkv + l * WL, nullptr, qkv, NROWS, 3 * EDIM, EDIM,
                 EDIM, 0, 0, 1, 0, 0, 1.f);
        attn_core(qkv, t1, t2,
                  enc_wo + (long long)l * EDIM * EDIM, enc_bo + l * EDIM,
                  src_pad, 0);
        ln_res_k<<<NROWS, 256>>>(x, t2, enc_lg + (l * 2 + 0) * EDIM, enc_lb + (l * 2 + 0) * EDIM);
        ffn_block(x, enc_w1 + (long long)l * EDIM * DFFD, enc_b1 + l * DFFD,
                  enc_w2 + (long long)l * DFFD * EDIM, enc_b2 + l * EDIM,
                  enc_lg + (l * 2 + 1) * EDIM, enc_lb + (l * 2 + 1) * EDIM, ff, t2);
    }

    for (int l = 0; l < NLD; l++) {
        // decoder self-attention (analytic causal + pad)
        gMain<1>(y, dqkv_s + l * WL, nullptr, qkv, NROWS, 3 * EDIM, EDIM,
                 EDIM, 0, 0, 1, 0, 0, 1.f);
        attn_core(qkv, t1, t2,
                  dwo_s + (long long)l * EDIM * EDIM, dbo_s + l * EDIM,
                  tgt_pad, 1);
        ln_res_k<<<NROWS, 256>>>(y, t2, dlg + (l * 3 + 0) * EDIM, dlb + (l * 3 + 0) * EDIM);

        // cross-attention: Q from y, K/V from encoder output x
        gTall<1>(y, dqkv_c + l * WL, nullptr, qkv, NROWS, EDIM, EDIM,
                 EDIM, 0, 0, 1, 0, 0, 1.f);
        gMain<1>(x, dqkv_c + l * WL + WS, nullptr, qkv, NROWS, 2 * EDIM, EDIM,
                 EDIM, 0, 0, 1, 0, 1024, 1.f);
        attn_core(qkv, t1, t2,
                  dwo_c + (long long)l * EDIM * EDIM, dbo_c + l * EDIM,
                  src_pad, 0);
        ln_res_k<<<NROWS, 256>>>(y, t2, dlg + (l * 3 + 1) * EDIM, dlb + (l * 3 + 1) * EDIM);

        ffn_block(y, dw1 + (long long)l * EDIM * DFFD, db1 + l * DFFD,
                  dw2 + (long long)l * DFFD * EDIM, db2 + l * EDIM,
                  dlg + (l * 3 + 2) * EDIM, dlb + (l * 3 + 2) * EDIM, ff, t2);
    }

    reorder_k<<<tg, 256>>>(y, (float*)d_out, 0);
}

// round 12
// speedup vs baseline: 4.8215x; 1.0333x over previous
#include <cuda_runtime.h>
#include <math.h>
#include <stdint.h>

// Problem constants
#define EDIM 1024
#define HN   16
#define DHD  64
#define DFFD 4096
#define NLE  4
#define NLD  4
#define NB   4
#define SEQ  512
#define NROWS (NB*SEQ)     // 2048
#define NBH   (NB*HN)      // 64
#define QKVOFF (NBH*SEQ*DHD)   // one q/k/v slab: 64*512*64 = 2M floats

// tf32-rounded weight slab offsets (floats)
#define W_EQKV 0LL
#define W_EWO  12582912LL
#define W_EW1  16777216LL
#define W_EW2  33554432LL
#define W_DQS  50331648LL
#define W_DWOS 62914560LL
#define W_DQC  67108864LL
#define W_DWOC 79691776LL
#define W_DW1  83886080LL
#define W_DW2  100663296LL
#define W_TOT  117440512LL

// ---------------- scratch (static device globals; no allocations) ----------
__device__ float g_x  [NB*SEQ*EDIM];
__device__ float g_y  [NB*SEQ*EDIM];
__device__ float g_xr [NB*SEQ*EDIM];              // tf32-rounded copy of x
__device__ float g_yr [NB*SEQ*EDIM];              // tf32-rounded copy of y
__device__ float g_qkv[3*QKVOFF];                 // q|k|v, each (B,H,S,DH)
__device__ float g_t1 [NB*SEQ*EDIM];              // flash out (pre-rounded)
__device__ float g_t2 [NB*SEQ*EDIM];
__device__ float g_ff [NB*SEQ*DFFD];              // relu out (pre-rounded)
__device__ float g_wtf[W_TOT];                    // tf32-rounded weights

// ---------------- small helpers ---------------------------------------------
__device__ __forceinline__ uint32_t f2tf(float x) {
    uint32_t r; asm("cvt.rna.tf32.f32 %0, %1;" : "=r"(r) : "f"(x)); return r;
}
__device__ __forceinline__ float tfr(float x) { return __uint_as_float(f2tf(x)); }
__device__ __forceinline__ uint4 cvt4(float4 v) {
    return make_uint4(f2tf(v.x), f2tf(v.y), f2tf(v.z), f2tf(v.w));
}
__device__ __forceinline__ void mma_tf32(float* c, const uint32_t* a, const uint32_t* b) {
    asm volatile("mma.sync.aligned.m16n8k8.row.col.f32.tf32.tf32.f32 "
                 "{%0,%1,%2,%3},{%4,%5,%6,%7},{%8,%9},{%0,%1,%2,%3};"
                 : "+f"(c[0]), "+f"(c[1]), "+f"(c[2]), "+f"(c[3])
                 : "r"(a[0]), "r"(a[1]), "r"(a[2]), "r"(a[3]), "r"(b[0]), "r"(b[1]));
}
__device__ __forceinline__ void cp_async16(uint32_t dst, const void* src) {
    asm volatile("cp.async.cg.shared.global [%0], [%1], 16;\n" :: "r"(dst), "l"(src));
}
__device__ __forceinline__ void cp_async8(uint32_t dst, const void* src) {
    asm volatile("cp.async.ca.shared.global [%0], [%1], 8;\n" :: "r"(dst), "l"(src));
}
__device__ __forceinline__ void cp_commit() {
    asm volatile("cp.async.commit_group;\n");
}
template<int N>
__device__ __forceinline__ void cp_wait() {
    asm volatile("cp.async.wait_group %0;\n" :: "n"(N));
}

__device__ __forceinline__ float blockReduceSum(float v) {
    __shared__ float sh[32];
    int lane = threadIdx.x & 31, w = threadIdx.x >> 5, nw = blockDim.x >> 5;
    #pragma unroll
    for (int o = 16; o; o >>= 1) v += __shfl_xor_sync(0xffffffffu, v, o);
    if (lane == 0) sh[w] = v;
    __syncthreads();
    if (w == 0) {
        float t = (lane < nw) ? sh[lane] : 0.f;
        #pragma unroll
        for (int o = 16; o; o >>= 1) t += __shfl_xor_sync(0xffffffffu, t, o);
        if (lane == 0) sh[0] = t;
    }
    __syncthreads();
    float r = sh[0]; __syncthreads(); return r;
}

// ---------------- tf32 round-copy (weights, once per launch) -----------------
__global__ void roundcopy_k(const float* __restrict__ in, float* __restrict__ out, int n4) {
    int i = blockIdx.x * blockDim.x + threadIdx.x;
    if (i < n4) {
        float4 v = ((const float4*)in)[i];
        ((float4*)out)[i] = make_float4(tfr(v.x), tfr(v.y), tfr(v.z), tfr(v.w));
    }
}

// ---------------- layout swap (S,B,E) <-> (B,S,E) ---------------------------
__global__ void reorder_k(const float* __restrict__ in, float* __restrict__ out,
                          float* __restrict__ outr, int toBS) {
    int s = blockIdx.x, b = blockIdx.y;
    long long r_sb = ((long long)s * NB + b) * EDIM;
    long long r_bs = ((long long)b * SEQ + s) * EDIM;
    long long ro = toBS ? r_bs : r_sb;
    const float4* src = (const float4*)(in + (toBS ? r_sb : r_bs));
    float4*       dst = (float4*)(out + ro);
    float4*       dstr = outr ? (float4*)(outr + ro) : nullptr;
    for (int i = threadIdx.x; i < EDIM / 4; i += blockDim.x) {
        float4 v = src[i];
        dst[i] = v;
        if (dstr) dstr[i] = make_float4(tfr(v.x), tfr(v.y), tfr(v.z), tfr(v.w));
    }
}

// ---------------- TF32 tensor-core GEMM, 4-stage cp.async pipeline ----------
// Inputs A and Bm MUST be pre-rounded to tf32 (raw bits fed to MMA).
// bMode: 0 = B row-major [k*ldb + n]; 1 = head-sliced weight (n>>6)*K*64+k*64+(n&63)
// cMode: 0 = C[m*ldc + n]; 1 = qkv scatter (+nOff) into unified (3,B,H,S,DH)
template<int BM, int BN, int BK, int STG, int WGN, int MT, int NT, int bMode>
__global__ __launch_bounds__(256, 2)
void tmma_k(const float* __restrict__ A, const float* __restrict__ Bm,
            const float* __restrict__ bias, float* __restrict__ C,
            int M, int N, int K, int lda, int ldb, int ldc,
            int cMode, int relu, int rOut, int nOff, float scale)
{
    constexpr int SAS   = BK + 4;
    constexpr int SBS   = BN + 8;
    constexpr int A_PER = (BM * BK) / 256;
    constexpr int STG_A = BM * SAS;
    constexpr int STG_B = BK * SBS;

    __shared__ float sA[STG][STG_A];
    __shared__ float sB[STG][STG_B];

    const int tid = threadIdx.x;
    const int row0 = blockIdx.y * BM, col0 = blockIdx.x * BN;
    const int w = tid >> 5, lane = tid & 31;
    const int gid = lane >> 2, tig = lane & 3;
    const int wm = w / WGN, wn = w % WGN;
    const int mBase = wm * MT * 16, nBase = wn * NT * 8;

    const int arA = (tid * A_PER) / BK, acA = (tid * A_PER) % BK;
    const int brB = (tid * 4) / BN,    bcB = (tid * 4) % BN;
    const float* aSrc = A + (long long)(row0 + arA) * lda + acA;
    const float* bSrc;
    if (bMode == 1) {
        int n = col0 + bcB; int h = n >> 6, dl = n & 63;
        bSrc = Bm + (long long)h * K * 64 + (long long)brB * 64 + dl;
    } else {
        bSrc = Bm + (long long)brB * ldb + col0 + bcB;
    }
    const long long bStep = (bMode == 0) ? (long long)BK * ldb : (long long)BK * 64;

    const uint32_t sAu = (uint32_t)__cvta_generic_to_shared(&sA[0][0])
                       + (uint32_t)(arA * SAS + acA) * 4u;
    const uint32_t sBu = (uint32_t)__cvta_generic_to_shared(&sB[0][0])
                       + (uint32_t)(brB * SBS + bcB) * 4u;

    float acc[MT][NT][4];
    #pragma unroll
    for (int i = 0; i < MT; i++)
        #pragma unroll
        for (int j = 0; j < NT; j++)
            #pragma unroll
            for (int r = 0; r < 4; r++) acc[i][j][r] = 0.f;

    const int nit = K / BK;

    #pragma unroll
    for (int s = 0; s < STG - 1; s++) {
        if (s < nit) {
            if (A_PER == 4) cp_async16(sAu + s * STG_A * 4, aSrc + s * BK);
            else            cp_async8 (sAu + s * STG_A * 4, aSrc + s * BK);
            cp_async16(sBu + s * STG_B * 4, bSrc + (long long)s * bStep);
        }
        cp_commit();
    }

    for (int it = 0; it < nit; it++) {
        cp_wait<STG - 2>();
        __syncthreads();

        const int buf = it % STG;
        const uint32_t* sAf = (const uint32_t*)sA[buf];
        const uint32_t* sBf = (const uint32_t*)sB[buf];

        uint32_t af[MT][4], bf[NT][2];
        #pragma unroll
        for (int mt = 0; mt < MT; mt++) {
            int m0 = mBase + mt * 16;
            af[mt][0] = sAf[(m0 + gid)     * SAS + tig];
            af[mt][1] = sAf[(m0 + gid + 8) * SAS + tig];
            af[mt][2] = sAf[(m0 + gid)     * SAS + tig + 4];
            af[mt][3] = sAf[(m0 + gid + 8) * SAS + tig + 4];
        }
        #pragma unroll
        for (int nt = 0; nt < NT; nt++) {
            int n0 = nBase + nt * 8;
            bf[nt][0] = sBf[tig       * SBS + n0 + gid];
            bf[nt][1] = sBf[(tig + 4) * SBS + n0 + gid];
        }
        #pragma unroll
        for (int mt = 0; mt < MT; mt++)
            #pragma unroll
            for (int nt = 0; nt < NT; nt++)
                mma_tf32(acc[mt][nt], af[mt], bf[nt]);

        const int nx = it + STG - 1;
        if (nx < nit) {
            const int nb = nx % STG;
            if (A_PER == 4) cp_async16(sAu + nb * STG_A * 4, aSrc + (long long)nx * BK);
            else            cp_async8 (sAu + nb * STG_A * 4, aSrc + (long long)nx * BK);
            cp_async16(sBu + nb * STG_B * 4, bSrc + (long long)nx * bStep);
        }
        cp_commit();
    }
    cp_wait<0>();   // drain before CTA exit

    #pragma unroll
    for (int mt = 0; mt < MT; mt++) {
        #pragma unroll
        for (int h2 = 0; h2 < 2; h2++) {
            int m = row0 + mBase + mt * 16 + gid + h2 * 8;
            #pragma unroll
            for (int nt = 0; nt < NT; nt++) {
                int n = col0 + nBase + nt * 8 + tig * 2;
                float v0 = acc[mt][nt][h2 * 2 + 0] * scale;
                float v1 = acc[mt][nt][h2 * 2 + 1] * scale;
                if (bias) { v0 += bias[n]; v1 += bias[n + 1]; }
                if (relu) { v0 = fmaxf(v0, 0.f); v1 = fmaxf(v1, 0.f); }
                if (rOut) { v0 = tfr(v0); v1 = tfr(v1); }
                if (cMode == 0) {
                    *(float2*)&C[(long long)m * ldc + n] = make_float2(v0, v1);
                } else {
                    int nq = n + nOff;
                    int which = nq >> 10, h = (nq >> 6) & 15;
                    int b = m >> 9, s = m & 511, d = n & 63;
                    *(float2*)&C[(long long)which * QKVOFF
                        + (((long long)(b * HN + h)) * SEQ + s) * DHD + d] = make_float2(v0, v1);
                }
            }
        }
    }
}

// ---------------- fused flash attention --------------------------------------
// grid (SEQ/128, NBH), 256 threads. out writes pre-rounded (tf32) values.
#define SKS 68
#define SVS 72
template<int CAUSAL>
__global__ __launch_bounds__(256, 2)
void flash_k(const float* __restrict__ q, const float* __restrict__ k,
             const float* __restrict__ v, const float* __restrict__ pad,
             float* __restrict__ out)
{
    __shared__ uint32_t sK[64 * SKS];
    __shared__ uint32_t sV[64 * SVS];
    __shared__ float sPad[64];

    const int tid  = threadIdx.x;
    const int w    = tid >> 5, lane = tid & 31;
    const int gid  = lane >> 2, tig = lane & 3;
    const int bh   = blockIdx.y;
    const int b    = bh >> 4, h = bh & 15;
    const int qbase = blockIdx.x * 128 + w * 16;
    const int row0 = qbase + gid, row1 = row0 + 8;

    uint32_t qf[8][4];
    {
        const float* qp = q + ((long long)bh * SEQ) * DHD;
        #pragma unroll
        for (int kk = 0; kk < 8; kk++) {
            qf[kk][0] = f2tf(0.125f * qp[(long long)row0 * DHD + kk * 8 + tig]);
            qf[kk][1] = f2tf(0.125f * qp[(long long)row1 * DHD + kk * 8 + tig]);
            qf[kk][2] = f2tf(0.125f * qp[(long long)row0 * DHD + kk * 8 + tig + 4]);
            qf[kk][3] = f2tf(0.125f * qp[(long long)row1 * DHD + kk * 8 + tig + 4]);
        }
    }

    float oacc[8][4];
    #pragma unroll
    for (int nt = 0; nt < 8; nt++)
        #pragma unroll
        for (int r = 0; r < 4; r++) oacc[nt][r] = 0.f;
    float m0 = -INFINITY, m1 = -INFINITY, l0 = 0.f, l1 = 0.f;

    const int Tend = CAUSAL ? (blockIdx.x * 128 + 128) : SEQ;

    for (int t0 = 0; t0 < Tend; t0 += 64) {
        {
            const float* kp = k + ((long long)bh * SEQ + t0) * DHD;
            const float* vp = v + ((long long)bh * SEQ + t0) * DHD;
            #pragma unroll
            for (int i = 0; i < 4; i++) {
                int e = (i * 256 + tid) * 4;
                int t = e >> 6, d = e & 63;
                float4 kv = *(const float4*)(kp + (long long)t * DHD + d);
                *(uint4*)&sK[t * SKS + d] = cvt4(kv);
                float4 vv = *(const float4*)(vp + (long long)t * DHD + d);
                *(uint4*)&sV[t * SVS + d] = cvt4(vv);
            }
            if (tid < 64) sPad[tid] = pad ? pad[b * SEQ + t0 + tid] : 0.f;
        }
        __syncthreads();

        float s[8][4];
        #pragma unroll
        for (int nt = 0; nt < 8; nt++)
            #pragma unroll
            for (int r = 0; r < 4; r++) s[nt][r] = 0.f;
        #pragma unroll
        for (int kk = 0; kk < 8; kk++) {
            #pragma unroll
            for (int nt = 0; nt < 8; nt++) {
                uint32_t bf[2];
                bf[0] = sK[(nt * 8 + gid) * SKS + kk * 8 + tig];
                bf[1] = sK[(nt * 8 + gid) * SKS + kk * 8 + tig + 4];
                mma_tf32(s[nt], qf[kk], bf);
            }
        }

        #pragma unroll
        for (int nt = 0; nt < 8; nt++) {
            int c0 = nt * 8 + 2 * tig, c1 = c0 + 1;
            float p0 = sPad[c0], p1 = sPad[c1];
            s[nt][0] += p0; s[nt][1] += p1;
            s[nt][2] += p0; s[nt][3] += p1;
            if (CAUSAL) {
                int tc0 = t0 + c0, tc1 = t0 + c1;
                if (tc0 > row0) s[nt][0] = -INFINITY;
                if (tc1 > row0) s[nt][1] = -INFINITY;
                if (tc0 > row1) s[nt][2] = -INFINITY;
                if (tc1 > row1) s[nt][3] = -INFINITY;
            }
        }

        float mt0 = -INFINITY, mt1 = -INFINITY;
        #pragma unroll
        for (int nt = 0; nt < 8; nt++) {
            mt0 = fmaxf(mt0, fmaxf(s[nt][0], s[nt][1]));
            mt1 = fmaxf(mt1, fmaxf(s[nt][2], s[nt][3]));
        }
        mt0 = fmaxf(mt0, __shfl_xor_sync(0xffffffffu, mt0, 1));
        mt0 = fmaxf(mt0, __shfl_xor_sync(0xffffffffu, mt0, 2));
        mt1 = fmaxf(mt1, __shfl_xor_sync(0xffffffffu, mt1, 1));
        mt1 = fmaxf(mt1, __shfl_xor_sync(0xffffffffu, mt1, 2));
        float mn0 = fmaxf(m0, mt0), mn1 = fmaxf(m1, mt1);
        float sc0 = __expf(m0 - mn0), sc1 = __expf(m1 - mn1);

        float rs0 = 0.f, rs1 = 0.f;
        #pragma unroll
        for (int nt = 0; nt < 8; nt++) {
            s[nt][0] = __expf(s[nt][0] - mn0);
            s[nt][1] = __expf(s[nt][1] - mn0);
            s[nt][2] = __expf(s[nt][2] - mn1);
            s[nt][3] = __expf(s[nt][3] - mn1);
            rs0 += s[nt][0] + s[nt][1];
            rs1 += s[nt][2] + s[nt][3];
        }
        rs0 += __shfl_xor_sync(0xffffffffu, rs0, 1);
        rs0 += __shfl_xor_sync(0xffffffffu, rs0, 2);
        rs1 += __shfl_xor_sync(0xffffffffu, rs1, 1);
        rs1 += __shfl_xor_sync(0xffffffffu, rs1, 2);
        l0 = l0 * sc0 + rs0;
        l1 = l1 * sc1 + rs1;
        m0 = mn0; m1 = mn1;
        #pragma unroll
        for (int nt = 0; nt < 8; nt++) {
            oacc[nt][0] *= sc0; oacc[nt][1] *= sc0;
            oacc[nt][2] *= sc1; oacc[nt][3] *= sc1;
        }

        const int qlane = lane & ~3;
        const int sl0 = qlane | (tig >> 1);
        const int sl1 = sl0 + 2;
        #pragma unroll
        for (int kk = 0; kk < 8; kk++) {
            float u00 = __shfl_sync(0xffffffffu, s[kk][0], sl0);
            float u01 = __shfl_sync(0xffffffffu, s[kk][1], sl0);
            float u02 = __shfl_sync(0xffffffffu, s[kk][0], sl1);
            float u03 = __shfl_sync(0xffffffffu, s[kk][1], sl1);
            float u10 = __shfl_sync(0xffffffffu, s[kk][2], sl0);
            float u11 = __shfl_sync(0xffffffffu, s[kk][3], sl0);
            float u12 = __shfl_sync(0xffffffffu, s[kk][2], sl1);
            float u13 = __shfl_sync(0xffffffffu, s[kk][3], sl1);
            uint32_t af[4];
            af[0] = f2tf((tig & 1) ? u01 : u00);
            af[1] = f2tf((tig & 1) ? u11 : u10);
            af[2] = f2tf((tig & 1) ? u03 : u02);
            af[3] = f2tf((tig & 1) ? u13 : u12);
            #pragma unroll
            for (int nt = 0; nt < 8; nt++) {
                uint32_t bf[2];
                bf[0] = sV[(kk * 8 + tig)     * SVS + nt * 8 + gid];
                bf[1] = sV[(kk * 8 + tig + 4) * SVS + nt * 8 + gid];
                mma_tf32(oacc[nt], af, bf);
            }
        }
        __syncthreads();
    }

    float inv0 = 1.f / l0, inv1 = 1.f / l1;
    float* o0 = out + ((long long)(b * SEQ + row0)) * EDIM + h * DHD;
    float* o1 = out + ((long long)(b * SEQ + row1)) * EDIM + h * DHD;
    #pragma unroll
    for (int nt = 0; nt < 8; nt++) {
        int c = nt * 8 + 2 * tig;
        *(float2*)(o0 + c) = make_float2(tfr(oacc[nt][0] * inv0), tfr(oacc[nt][1] * inv0));
        *(float2*)(o1 + c) = make_float2(tfr(oacc[nt][2] * inv1), tfr(oacc[nt][3] * inv1));
    }
}

// ---------------- fused residual + LayerNorm (in-place, + rounded copy) -----
__global__ void ln_res_k(float* __restrict__ x, const float* __restrict__ d,
                         const float* __restrict__ g, const float* __restrict__ b,
                         float* __restrict__ xr)
{
    long long row = blockIdx.x;
    float* xp = x + row * EDIM;
    const float* dr = d + row * EDIM;
    int t = threadIdx.x;
    float4 xv = ((float4*)xp)[t];
    float4 dv = ((const float4*)dr)[t];
    float v0 = xv.x + dv.x, v1 = xv.y + dv.y, v2 = xv.z + dv.z, v3 = xv.w + dv.w;
    float mean = blockReduceSum(v0 + v1 + v2 + v3) * (1.f / EDIM);
    float c0 = v0 - mean, c1 = v1 - mean, c2 = v2 - mean, c3 = v3 - mean;
    float var = blockReduceSum(c0 * c0 + c1 * c1 + c2 * c2 + c3 * c3) * (1.f / EDIM);
    float rstd = rsqrtf(var + 1e-5f);
    float4 gv = ((const float4*)g)[t];
    float4 bv = ((const float4*)b)[t];
    float4 o = make_float4(c0 * rstd * gv.x + bv.x, c1 * rstd * gv.y + bv.y,
                           c2 * rstd * gv.z + bv.z, c3 * rstd * gv.w + bv.w);
    ((float4*)xp)[t] = o;
    ((float4*)(xr + row * EDIM))[t] = make_float4(tfr(o.x), tfr(o.y), tfr(o.z), tfr(o.w));
}

// ---------------- host-side launch helpers ----------------------------------
template<int bMode>
static inline void gMain(const float* A, const float* Bm, const float* bias, float* C,
                         int M, int N, int K, int lda, int ldb, int ldc,
                         int cMode, int relu, int rOut, int nOff, float scale)
{
    dim3 grid(N / 128, M / 128, 1);
    tmma_k<128, 128, 8, 4, 4, 4, 4, bMode><<<grid, 256>>>(
        A, Bm, bias, C, M, N, K, lda, ldb, ldc, cMode, relu, rOut, nOff, scale);
}
template<int bMode>
static inline void gTall(const float* A, const float* Bm, const float* bias, float* C,
                         int M, int N, int K, int lda, int ldb, int ldc,
                         int cMode, int relu, int rOut, int nOff, float scale)
{
    dim3 grid(N / 128, M / 64, 1);
    tmma_k<64, 128, 8, 4, 4, 2, 4, bMode><<<grid, 256>>>(
        A, Bm, bias, C, M, N, K, lda, ldb, ldc, cMode, relu, rOut, nOff, scale);
}

static inline void roundcopy(const float* src, float* dst, long long n) {
    int n4 = (int)(n / 4);
    roundcopy_k<<<(n4 + 255) / 256, 256>>>(src, dst, n4);
}

// attention core after q/k/v are in g_qkv; t1 written pre-rounded by flash
static void attn_core(float* qkv, float* t1, float* t2,
                      const float* wo, const float* bo,
                      const float* pad, int causal)
{
    float* q = qkv;
    float* k = qkv + QKVOFF;
    float* v = qkv + 2 * QKVOFF;
    dim3 fg(SEQ / 128, NBH);
    if (causal) flash_k<1><<<fg, 256>>>(q, k, v, pad, t1);
    else        flash_k<0><<<fg, 256>>>(q, k, v, pad, t1);
    gTall<0>(t1, wo, bo, t2, NROWS, EDIM, EDIM, EDIM, EDIM, EDIM, 0, 0, 0, 0, 1.f);
}

static void ffn_block(float* x, float* xr, const float* w1, const float* b1,
                      const float* w2, const float* b2,
                      const float* lg, const float* lb, float* ff, float* t2)
{
    gMain<0>(xr, w1, b1, ff, NROWS, DFFD, EDIM, EDIM, DFFD, DFFD, 0, 1, 1, 0, 1.f);
    gTall<0>(ff, w2, b2, t2, NROWS, EDIM, DFFD, DFFD, EDIM, EDIM, 0, 0, 0, 0, 1.f);
    ln_res_k<<<NROWS, 256>>>(x, t2, lg, lb, xr);
}

// ---------------- entry -----------------------------------------------------
extern "C" void kernel_launch(void* const* d_in, const int* in_sizes, int n_in,
                              void* d_out, int out_size)
{
    const float* src      = (const float*)d_in[0];
    const float* tgt      = (const float*)d_in[1];
    const float* src_pad  = (const float*)d_in[4];
    const float* tgt_pad  = (const float*)d_in[5];
    const float* enc_wqkv = (const float*)d_in[6];
    const float* enc_wo   = (const float*)d_in[7];
    const float* enc_bo   = (const float*)d_in[8];
    const float* enc_w1   = (const float*)d_in[9];
    const float* enc_b1   = (const float*)d_in[10];
    const float* enc_w2   = (const float*)d_in[11];
    const float* enc_b2   = (const float*)d_in[12];
    const float* enc_lg   = (const float*)d_in[13];
    const float* enc_lb   = (const float*)d_in[14];
    const float* dqkv_s   = (const float*)d_in[15];
    const float* dwo_s    = (const float*)d_in[16];
    const float* dbo_s    = (const float*)d_in[17];
    const float* dqkv_c   = (const float*)d_in[18];
    const float* dwo_c    = (const float*)d_in[19];
    const float* dbo_c    = (const float*)d_in[20];
    const float* dw1      = (const float*)d_in[21];
    const float* db1      = (const float*)d_in[22];
    const float* dw2      = (const float*)d_in[23];
    const float* db2      = (const float*)d_in[24];
    const float* dlg      = (const float*)d_in[25];
    const float* dlb      = (const float*)d_in[26];

    float *x, *y, *xr, *yr, *qkv, *t1, *t2, *ff, *wtf;
    cudaGetSymbolAddress((void**)&x,   g_x);
    cudaGetSymbolAddress((void**)&y,   g_y);
    cudaGetSymbolAddress((void**)&xr,  g_xr);
    cudaGetSymbolAddress((void**)&yr,  g_yr);
    cudaGetSymbolAddress((void**)&qkv, g_qkv);
    cudaGetSymbolAddress((void**)&t1,  g_t1);
    cudaGetSymbolAddress((void**)&t2,  g_t2);
    cudaGetSymbolAddress((void**)&ff,  g_ff);
    cudaGetSymbolAddress((void**)&wtf, g_wtf);

    // ---- pre-round all weights to tf32 (one pass) ----
    roundcopy(enc_wqkv, wtf + W_EQKV, 12582912LL);
    roundcopy(enc_wo,   wtf + W_EWO,   4194304LL);
    roundcopy(enc_w1,   wtf + W_EW1,  16777216LL);
    roundcopy(enc_w2,   wtf + W_EW2,  16777216LL);
    roundcopy(dqkv_s,   wtf + W_DQS,  12582912LL);
    roundcopy(dwo_s,    wtf + W_DWOS,  4194304LL);
    roundcopy(dqkv_c,   wtf + W_DQC,  12582912LL);
    roundcopy(dwo_c,    wtf + W_DWOC,  4194304LL);
    roundcopy(dw1,      wtf + W_DW1,  16777216LL);
    roundcopy(dw2,      wtf + W_DW2,  16777216LL);

    dim3 tg(SEQ, NB);
    reorder_k<<<tg, 256>>>(src, x, xr, 1);
    reorder_k<<<tg, 256>>>(tgt, y, yr, 1);

    const long long WL = (long long)3 * HN * EDIM * DHD;  // per-layer wqkv slab
    const long long WS = (long long)HN * EDIM * DHD;      // one of q/k/v
    const long long WO = (long long)EDIM * EDIM;
    const long long W1 = (long long)EDIM * DFFD;

    for (int l = 0; l < NLE; l++) {
        gMain<1>(xr, wtf + W_EQKV + l * WL, nullptr, qkv, NROWS, 3 * EDIM, EDIM,
                 EDIM, 0, 0, 1, 0, 0, 0, 1.f);
        attn_core(qkv, t1, t2, wtf + W_EWO + l * WO, enc_bo + l * EDIM, src_pad, 0);
        ln_res_k<<<NROWS, 256>>>(x, t2, enc_lg + (l * 2 + 0) * EDIM,
                                 enc_lb + (l * 2 + 0) * EDIM, xr);
        ffn_block(x, xr, wtf + W_EW1 + l * W1, enc_b1 + l * DFFD,
                  wtf + W_EW2 + l * W1, enc_b2 + l * EDIM,
                  enc_lg + (l * 2 + 1) * EDIM, enc_lb + (l * 2 + 1) * EDIM, ff, t2);
    }

    for (int l = 0; l < NLD; l++) {
        // decoder self-attention (analytic causal + pad)
        gMain<1>(yr, wtf + W_DQS + l * WL, nullptr, qkv, NROWS, 3 * EDIM, EDIM,
                 EDIM, 0, 0, 1, 0, 0, 0, 1.f);
        attn_core(qkv, t1, t2, wtf + W_DWOS + l * WO, dbo_s + l * EDIM, tgt_pad, 1);
        ln_res_k<<<NROWS, 256>>>(y, t2, dlg + (l * 3 + 0) * EDIM,
                                 dlb + (l * 3 + 0) * EDIM, yr);

        // cross-attention: Q from y, K/V from encoder output x
        gTall<1>(yr, wtf + W_DQC + l * WL, nullptr, qkv, NROWS, EDIM, EDIM,
                 EDIM, 0, 0, 1, 0, 0, 0, 1.f);
        gMain<1>(xr, wtf + W_DQC + l * WL + WS, nullptr, qkv, NROWS, 2 * EDIM, EDIM,
                 EDIM, 0, 0, 1, 0, 0, 1024, 1.f);
        attn_core(qkv, t1, t2, wtf + W_DWOC + l * WO, dbo_c + l * EDIM, src_pad, 0);
        ln_res_k<<<NROWS, 256>>>(y, t2, dlg + (l * 3 + 1) * EDIM,
                                 dlb + (l * 3 + 1) * EDIM, yr);

        ffn_block(y, yr, wtf + W_DW1 + l * W1, db1 + l * DFFD,
                  wtf + W_DW2 + l * W1, db2 + l * EDIM,
                  dlg + (l * 3 + 2) * EDIM, dlb + (l * 3 + 2) * EDIM, ff, t2);
    }

    reorder_k<<<tg, 256>>>(y, (float*)d_out, nullptr, 0);
}